// round 2
// baseline (speedup 1.0000x reference)
#include <cuda_runtime.h>
#include <cuda_bf16.h>

// ---------------------------------------------------------------------------
// GAT encoder: 2x GATConv (4 heads x 32, then 1 head x 256), ReLU between.
// N=50000 nodes, E=1.6M edges + N self-loops. fp32 throughout.
// edge_index is int32 (JAX default x64-disabled downcasts int64 -> int32).
// ---------------------------------------------------------------------------

#define NNODES 50000
#define EMAX   1700000   // >= E + N

// Scratch (device globals; allocation inside kernel_launch is forbidden)
__device__ __align__(16) float g_hlin1[NNODES * 128];   // x @ W1
__device__ __align__(16) float g_als1[NNODES * 4];      // alpha_src layer1 [N,4]
__device__ __align__(16) float g_ald1[NNODES * 4];      // alpha_dst layer1 [N,4]
__device__ __align__(16) float g_e1[EMAX * 4];          // exp(logit) layer1 [E,4]
__device__ __align__(16) float g_s1[NNODES * 4];        // softmax denom layer1
__device__ __align__(16) float g_agg1[NNODES * 128];    // aggregated layer1 (then relu in place)
__device__ __align__(16) float g_hlin2[NNODES * 256];   // h @ W2
__device__ __align__(16) float g_als2[NNODES];
__device__ __align__(16) float g_ald2[NNODES];
__device__ __align__(16) float g_e2[EMAX];
__device__ __align__(16) float g_s2[NNODES];
__device__ int g_src[EMAX];
__device__ int g_dst[EMAX];

__device__ __forceinline__ float lrelu(float x) {
    return x > 0.0f ? x : 0.2f * x;
}

// ---------------------------------------------------------------------------
// Zero init: d_out, agg1, s1, s2
// ---------------------------------------------------------------------------
__global__ void zero_all(float* __restrict__ out, int nout,
                         float* __restrict__ agg, int nagg,
                         float* __restrict__ s1, int ns1,
                         float* __restrict__ s2, int ns2) {
    int i = blockIdx.x * blockDim.x + threadIdx.x;
    if (i < nout) out[i] = 0.0f;
    if (i < nagg) agg[i] = 0.0f;
    if (i < ns1)  s1[i]  = 0.0f;
    if (i < ns2)  s2[i]  = 0.0f;
}

// ---------------------------------------------------------------------------
// SGEMM: C[M, Ncols] = A[M,128] @ B[128, Ncols].  K=128 fixed.
// 128x128 block tile, 8x8 per thread, 256 threads.
// ---------------------------------------------------------------------------
__global__ __launch_bounds__(256, 1)
void sgemm_k128(const float* __restrict__ A, const float* __restrict__ B,
                float* __restrict__ C, int M, int Ncols) {
    __shared__ float As[8][128];
    __shared__ float Bs[8][128];

    const int tid  = threadIdx.x;
    const int row0 = blockIdx.x * 128;
    const int col0 = blockIdx.y * 128;
    const int ty = tid >> 4;          // 0..15
    const int tx = tid & 15;          // 0..15

    const int lrow = tid >> 1;        // 0..127  (A load)
    const int lkh  = (tid & 1) * 4;   // 0 or 4
    const int bk   = tid >> 5;        // 0..7    (B load)
    const int bc   = (tid & 31) * 4;  // 0..124

    float acc[8][8];
    #pragma unroll
    for (int i = 0; i < 8; i++)
        #pragma unroll
        for (int j = 0; j < 8; j++) acc[i][j] = 0.0f;

    for (int kc = 0; kc < 128; kc += 8) {
        float4 av = make_float4(0.f, 0.f, 0.f, 0.f);
        int gr = row0 + lrow;
        if (gr < M) av = *(const float4*)&A[(size_t)gr * 128 + kc + lkh];
        As[lkh + 0][lrow] = av.x;
        As[lkh + 1][lrow] = av.y;
        As[lkh + 2][lrow] = av.z;
        As[lkh + 3][lrow] = av.w;

        float4 bv = *(const float4*)&B[(size_t)(kc + bk) * Ncols + col0 + bc];
        *(float4*)&Bs[bk][bc] = bv;

        __syncthreads();

        #pragma unroll
        for (int k = 0; k < 8; k++) {
            float a[8], b[8];
            *(float4*)&a[0] = *(const float4*)&As[k][ty * 8];
            *(float4*)&a[4] = *(const float4*)&As[k][ty * 8 + 4];
            *(float4*)&b[0] = *(const float4*)&Bs[k][tx * 8];
            *(float4*)&b[4] = *(const float4*)&Bs[k][tx * 8 + 4];
            #pragma unroll
            for (int i = 0; i < 8; i++)
                #pragma unroll
                for (int j = 0; j < 8; j++)
                    acc[i][j] = fmaf(a[i], b[j], acc[i][j]);
        }
        __syncthreads();
    }

    #pragma unroll
    for (int i = 0; i < 8; i++) {
        int gr = row0 + ty * 8 + i;
        if (gr < M) {
            float4 v0 = make_float4(acc[i][0], acc[i][1], acc[i][2], acc[i][3]);
            float4 v1 = make_float4(acc[i][4], acc[i][5], acc[i][6], acc[i][7]);
            *(float4*)&C[(size_t)gr * Ncols + col0 + tx * 8]     = v0;
            *(float4*)&C[(size_t)gr * Ncols + col0 + tx * 8 + 4] = v1;
        }
    }
}

// ---------------------------------------------------------------------------
// Layer-1 node attention terms: al[n][h] = sum_c h[n, h*32+c] * a[h][c]
// One block (128 threads = 4 warps = 4 heads) per node.
// ---------------------------------------------------------------------------
__global__ void node_alpha1(const float* __restrict__ h,
                            const float* __restrict__ a_src,
                            const float* __restrict__ a_dst,
                            float* __restrict__ al_s,
                            float* __restrict__ al_d, int N) {
    int n = blockIdx.x;
    if (n >= N) return;
    int c = threadIdx.x;          // 0..127
    float v = h[n * 128 + c];
    float ps = v * a_src[c];
    float pd = v * a_dst[c];
    #pragma unroll
    for (int off = 16; off > 0; off >>= 1) {
        ps += __shfl_down_sync(0xFFFFFFFFu, ps, off);
        pd += __shfl_down_sync(0xFFFFFFFFu, pd, off);
    }
    if ((c & 31) == 0) {
        int hidx = c >> 5;
        al_s[n * 4 + hidx] = ps;
        al_d[n * 4 + hidx] = pd;
    }
}

// ---------------------------------------------------------------------------
// Layer-2 node attention terms: dot over 256, one block per node.
// ---------------------------------------------------------------------------
__global__ void node_alpha2(const float* __restrict__ h,
                            const float* __restrict__ a_src,
                            const float* __restrict__ a_dst,
                            float* __restrict__ al_s,
                            float* __restrict__ al_d, int N) {
    int n = blockIdx.x;
    if (n >= N) return;
    int c = threadIdx.x;          // 0..255
    float v = h[n * 256 + c];
    float ps = v * a_src[c];
    float pd = v * a_dst[c];
    #pragma unroll
    for (int off = 16; off > 0; off >>= 1) {
        ps += __shfl_down_sync(0xFFFFFFFFu, ps, off);
        pd += __shfl_down_sync(0xFFFFFFFFu, pd, off);
    }
    __shared__ float ss[8], sd[8];
    if ((c & 31) == 0) { ss[c >> 5] = ps; sd[c >> 5] = pd; }
    __syncthreads();
    if (c == 0) {
        float a = 0.f, b = 0.f;
        #pragma unroll
        for (int i = 0; i < 8; i++) { a += ss[i]; b += sd[i]; }
        al_s[n] = a;
        al_d[n] = b;
    }
}

// ---------------------------------------------------------------------------
// Layer-1 edge pass: logits -> exp, accumulate softmax denominator.
// Also materializes src/dst (incl. self loops) for later passes.
// edge_index arrives as int32: ei[0..E) = src, ei[E..2E) = dst.
// ---------------------------------------------------------------------------
__global__ void edge_pass1(const int* __restrict__ ei, int E, int Etot,
                           const float* __restrict__ als,
                           const float* __restrict__ ald,
                           float* __restrict__ e1, float* __restrict__ s1,
                           int* __restrict__ gsrc, int* __restrict__ gdst) {
    int i = blockIdx.x * blockDim.x + threadIdx.x;
    if (i >= Etot) return;
    int s, d;
    if (i < E) {
        s = ei[i];
        d = ei[E + i];
    } else {
        s = d = i - E;
    }
    gsrc[i] = s;
    gdst[i] = d;
    float4 as = *(const float4*)&als[s * 4];
    float4 ad = *(const float4*)&ald[d * 4];
    float4 e;
    e.x = __expf(lrelu(as.x + ad.x));
    e.y = __expf(lrelu(as.y + ad.y));
    e.z = __expf(lrelu(as.z + ad.z));
    e.w = __expf(lrelu(as.w + ad.w));
    *(float4*)&e1[i * 4] = e;
    atomicAdd((float4*)&s1[d * 4], e);
}

// ---------------------------------------------------------------------------
// Layer-1 aggregation: one warp per edge, 4 floats (1 head-quarter) per lane.
// ---------------------------------------------------------------------------
__global__ void agg_pass1(const int* __restrict__ gsrc, const int* __restrict__ gdst,
                          const float* __restrict__ e1, const float* __restrict__ s1,
                          const float* __restrict__ hlin, float* __restrict__ agg,
                          int Etot) {
    int w = (blockIdx.x * blockDim.x + threadIdx.x) >> 5;
    int lane = threadIdx.x & 31;
    if (w >= Etot) return;
    int s = gsrc[w], d = gdst[w];
    int head = lane >> 3;
    float alpha = e1[w * 4 + head] / (s1[d * 4 + head] + 1e-16f);
    float4 v = *(const float4*)&hlin[s * 128 + lane * 4];
    v.x *= alpha; v.y *= alpha; v.z *= alpha; v.w *= alpha;
    atomicAdd((float4*)&agg[d * 128 + lane * 4], v);
}

// bias + relu in place on agg1
__global__ void bias_relu1(float* __restrict__ agg, const float* __restrict__ b, int n) {
    int i = blockIdx.x * blockDim.x + threadIdx.x;
    if (i < n) {
        float v = agg[i] + b[i & 127];
        agg[i] = v > 0.f ? v : 0.f;
    }
}

// ---------------------------------------------------------------------------
// Layer-2 edge pass
// ---------------------------------------------------------------------------
__global__ void edge_pass2(const int* __restrict__ gsrc, const int* __restrict__ gdst,
                           const float* __restrict__ als, const float* __restrict__ ald,
                           float* __restrict__ e2, float* __restrict__ s2, int Etot) {
    int i = blockIdx.x * blockDim.x + threadIdx.x;
    if (i >= Etot) return;
    int s = gsrc[i], d = gdst[i];
    float e = __expf(lrelu(als[s] + ald[d]));
    e2[i] = e;
    atomicAdd(&s2[d], e);
}

// ---------------------------------------------------------------------------
// Layer-2 aggregation: one warp per edge, 8 floats per lane (256 total).
// ---------------------------------------------------------------------------
__global__ void agg_pass2(const int* __restrict__ gsrc, const int* __restrict__ gdst,
                          const float* __restrict__ e2, const float* __restrict__ s2,
                          const float* __restrict__ hlin, float* __restrict__ out,
                          int Etot) {
    int w = (blockIdx.x * blockDim.x + threadIdx.x) >> 5;
    int lane = threadIdx.x & 31;
    if (w >= Etot) return;
    int s = gsrc[w], d = gdst[w];
    float alpha = e2[w] / (s2[d] + 1e-16f);
    const float* hp = &hlin[s * 256 + lane * 8];
    float* op = &out[d * 256 + lane * 8];
    float4 v0 = *(const float4*)&hp[0];
    float4 v1 = *(const float4*)&hp[4];
    v0.x *= alpha; v0.y *= alpha; v0.z *= alpha; v0.w *= alpha;
    v1.x *= alpha; v1.y *= alpha; v1.z *= alpha; v1.w *= alpha;
    atomicAdd((float4*)&op[0], v0);
    atomicAdd((float4*)&op[4], v1);
}

__global__ void bias2(float* __restrict__ out, const float* __restrict__ b, int n) {
    int i = blockIdx.x * blockDim.x + threadIdx.x;
    if (i < n) out[i] += b[i & 255];
}

// ---------------------------------------------------------------------------
// Launch
// ---------------------------------------------------------------------------
extern "C" void kernel_launch(void* const* d_in, const int* in_sizes, int n_in,
                              void* d_out, int out_size) {
    const float* x   = (const float*)d_in[0];
    const int*   ei  = (const int*)d_in[1];
    const float* W1  = (const float*)d_in[2];
    const float* as1 = (const float*)d_in[3];
    const float* ad1 = (const float*)d_in[4];
    const float* b1  = (const float*)d_in[5];
    const float* W2  = (const float*)d_in[6];
    const float* as2 = (const float*)d_in[7];
    const float* ad2 = (const float*)d_in[8];
    const float* b2  = (const float*)d_in[9];
    float* out = (float*)d_out;

    const int N    = in_sizes[0] / 128;   // 50000
    const int E    = in_sizes[1] / 2;     // 1600000
    const int Etot = E + N;               // 1650000

    // scratch pointers
    float *hlin1, *als1p, *ald1p, *e1, *s1, *agg1, *hlin2, *als2p, *ald2p, *e2, *s2;
    int *srcp, *dstp;
    cudaGetSymbolAddress((void**)&hlin1, g_hlin1);
    cudaGetSymbolAddress((void**)&als1p, g_als1);
    cudaGetSymbolAddress((void**)&ald1p, g_ald1);
    cudaGetSymbolAddress((void**)&e1,    g_e1);
    cudaGetSymbolAddress((void**)&s1,    g_s1);
    cudaGetSymbolAddress((void**)&agg1,  g_agg1);
    cudaGetSymbolAddress((void**)&hlin2, g_hlin2);
    cudaGetSymbolAddress((void**)&als2p, g_als2);
    cudaGetSymbolAddress((void**)&ald2p, g_ald2);
    cudaGetSymbolAddress((void**)&e2,    g_e2);
    cudaGetSymbolAddress((void**)&s2,    g_s2);
    cudaGetSymbolAddress((void**)&srcp,  g_src);
    cudaGetSymbolAddress((void**)&dstp,  g_dst);

    const int nout  = N * 256;
    const int nagg  = N * 128;

    // 0) zero accumulators
    zero_all<<<(nout + 255) / 256, 256>>>(out, nout, agg1, nagg, s1, N * 4, s2, N);

    // 1) h_lin1 = x @ W1   [N,128]
    {
        dim3 grid((N + 127) / 128, 1);
        sgemm_k128<<<grid, 256>>>(x, W1, hlin1, N, 128);
    }

    // 2) node attention terms layer1
    node_alpha1<<<N, 128>>>(hlin1, as1, ad1, als1p, ald1p, N);

    // 3) edge logits / exp / denom layer1 (+ src/dst incl. self-loops)
    edge_pass1<<<(Etot + 255) / 256, 256>>>(ei, E, Etot, als1p, ald1p, e1, s1, srcp, dstp);

    // 4) aggregation layer1 (warp per edge)
    agg_pass1<<<(Etot * 32 + 255) / 256, 256>>>(srcp, dstp, e1, s1, hlin1, agg1, Etot);

    // 5) bias + relu in place
    bias_relu1<<<(nagg + 255) / 256, 256>>>(agg1, b1, nagg);

    // 6) h_lin2 = h_act1 @ W2   [N,256]
    {
        dim3 grid((N + 127) / 128, 2);
        sgemm_k128<<<grid, 256>>>(agg1, W2, hlin2, N, 256);
    }

    // 7) node attention terms layer2
    node_alpha2<<<N, 256>>>(hlin2, as2, ad2, als2p, ald2p, N);

    // 8) edge logits / exp / denom layer2
    edge_pass2<<<(Etot + 255) / 256, 256>>>(srcp, dstp, als2p, ald2p, e2, s2, Etot);

    // 9) aggregation layer2 into d_out
    agg_pass2<<<(Etot * 32 + 255) / 256, 256>>>(srcp, dstp, e2, s2, hlin2, out, Etot);

    // 10) + bias2
    bias2<<<(nout + 255) / 256, 256>>>(out, b2, nout);
}

// round 3
// speedup vs baseline: 2.3459x; 2.3459x over previous
#include <cuda_runtime.h>
#include <cuda_bf16.h>

// ---------------------------------------------------------------------------
// GAT encoder: 2x GATConv (4 heads x 32, then 1 head x 256), ReLU between.
// N=50000 nodes, E=1.6M edges + N self-loops. fp32.
// R2: CSR (dst-bucketed) gather aggregation -- no float atomics anywhere.
//     f32x2 packed-FFMA SGEMM (Blackwell fma.rn.f32x2).
// ---------------------------------------------------------------------------

#define NNODES 50000
#define EMAX   1700000   // >= E + N

// Scratch (device globals; allocation inside kernel_launch is forbidden)
__device__ __align__(16) float g_hlin1[NNODES * 128];   // x @ W1
__device__ __align__(16) float g_als1[NNODES * 4];      // alpha_src layer1 [N,4]
__device__ __align__(16) float g_ald1[NNODES * 4];      // alpha_dst layer1 [N,4]
__device__ __align__(16) float g_agg1[NNODES * 128];    // layer1 output (post bias+relu)
__device__ __align__(16) float g_hlin2[NNODES * 256];   // h @ W2
__device__ __align__(16) float g_als2[NNODES];
__device__ __align__(16) float g_ald2[NNODES];
__device__ int g_count[NNODES];          // per-dst in-degree
__device__ int g_rowstart[NNODES + 1];   // CSR row offsets
__device__ int g_cursor[NNODES];         // scatter cursors
__device__ int g_sorted_src[EMAX];       // src node per CSR slot

__device__ __forceinline__ float lrelu(float x) {
    return x > 0.0f ? x : 0.2f * x;
}

__device__ __forceinline__ unsigned long long pack2(float x, float y) {
    unsigned long long r;
    asm("mov.b64 %0, {%1, %2};" : "=l"(r) : "f"(x), "f"(y));
    return r;
}
__device__ __forceinline__ void fma2(unsigned long long& d,
                                     unsigned long long a, unsigned long long b) {
    asm("fma.rn.f32x2 %0, %1, %2, %0;" : "+l"(d) : "l"(a), "l"(b));
}
__device__ __forceinline__ void unpack2(unsigned long long v, float& lo, float& hi) {
    asm("mov.b64 {%0, %1}, %2;" : "=f"(lo), "=f"(hi) : "l"(v));
}
__device__ __forceinline__ float sel4(float4 v, int h) {
    float r = v.x;
    r = (h == 1) ? v.y : r;
    r = (h == 2) ? v.z : r;
    r = (h == 3) ? v.w : r;
    return r;
}

// ---------------------------------------------------------------------------
// CSR build
// ---------------------------------------------------------------------------
__global__ void zero_counts(int* __restrict__ cnt, int n) {
    int i = blockIdx.x * blockDim.x + threadIdx.x;
    if (i < n) cnt[i] = 0;
}

__global__ void hist_dst(const int* __restrict__ ei, int E, int Etot,
                         int* __restrict__ cnt) {
    int i = blockIdx.x * blockDim.x + threadIdx.x;
    if (i >= Etot) return;
    int d = (i < E) ? ei[E + i] : (i - E);
    atomicAdd(&cnt[d], 1);
}

// single-block exclusive scan of cnt[0..N) -> rowstart[0..N], cursor copy
__global__ __launch_bounds__(1024, 1)
void scan_counts(const int* __restrict__ cnt, int* __restrict__ rowstart,
                 int* __restrict__ cursor, int N) {
    __shared__ int wsum[32];
    __shared__ int s_carry;
    const int tid = threadIdx.x, lane = tid & 31, wid = tid >> 5;
    if (tid == 0) s_carry = 0;
    __syncthreads();
    for (int base = 0; base < N; base += 1024) {
        int i = base + tid;
        int v = (i < N) ? cnt[i] : 0;
        int x = v;
        #pragma unroll
        for (int off = 1; off < 32; off <<= 1) {
            int y = __shfl_up_sync(0xFFFFFFFFu, x, off);
            if (lane >= off) x += y;
        }
        if (lane == 31) wsum[wid] = x;
        __syncthreads();
        if (wid == 0) {
            int w = wsum[lane];
            #pragma unroll
            for (int off = 1; off < 32; off <<= 1) {
                int y = __shfl_up_sync(0xFFFFFFFFu, w, off);
                if (lane >= off) w += y;
            }
            wsum[lane] = w;   // inclusive across warps
        }
        __syncthreads();
        int carry = s_carry;
        int excl = carry + (wid > 0 ? wsum[wid - 1] : 0) + x - v;
        if (i < N) { rowstart[i] = excl; cursor[i] = excl; }
        __syncthreads();
        if (tid == 1023) s_carry = carry + wsum[31];
        __syncthreads();
    }
    if (tid == 0) rowstart[N] = s_carry;
}

__global__ void scatter_edges(const int* __restrict__ ei, int E, int Etot,
                              int* __restrict__ cursor,
                              int* __restrict__ sorted_src) {
    int i = blockIdx.x * blockDim.x + threadIdx.x;
    if (i >= Etot) return;
    int s, d;
    if (i < E) { s = ei[i]; d = ei[E + i]; }
    else       { s = d = i - E; }
    int pos = atomicAdd(&cursor[d], 1);
    sorted_src[pos] = s;
}

// ---------------------------------------------------------------------------
// SGEMM: C[M,Ncols] = A[M,128] @ B[128,Ncols]. K=128. f32x2 packed FMA.
// 128x128 block tile, 8x8 per thread, 256 threads.
// ---------------------------------------------------------------------------
__global__ __launch_bounds__(256, 1)
void sgemm_k128(const float* __restrict__ A, const float* __restrict__ B,
                float* __restrict__ C, int M, int Ncols) {
    __shared__ float As[8][128];
    __shared__ float Bs[8][128];

    const int tid  = threadIdx.x;
    const int row0 = blockIdx.x * 128;
    const int col0 = blockIdx.y * 128;
    const int ty = tid >> 4;          // 0..15
    const int tx = tid & 15;          // 0..15

    const int lrow = tid >> 1;        // 0..127  (A load)
    const int lkh  = (tid & 1) * 4;   // 0 or 4
    const int bk   = tid >> 5;        // 0..7    (B load)
    const int bc   = (tid & 31) * 4;  // 0..124

    unsigned long long acc2[8][4];
    #pragma unroll
    for (int i = 0; i < 8; i++)
        #pragma unroll
        for (int j = 0; j < 4; j++) acc2[i][j] = 0ULL;

    for (int kc = 0; kc < 128; kc += 8) {
        float4 av = make_float4(0.f, 0.f, 0.f, 0.f);
        int gr = row0 + lrow;
        if (gr < M) av = *(const float4*)&A[(size_t)gr * 128 + kc + lkh];
        As[lkh + 0][lrow] = av.x;
        As[lkh + 1][lrow] = av.y;
        As[lkh + 2][lrow] = av.z;
        As[lkh + 3][lrow] = av.w;

        float4 bv = *(const float4*)&B[(size_t)(kc + bk) * Ncols + col0 + bc];
        *(float4*)&Bs[bk][bc] = bv;

        __syncthreads();

        #pragma unroll
        for (int k = 0; k < 8; k++) {
            float a[8];
            *(float4*)&a[0] = *(const float4*)&As[k][ty * 8];
            *(float4*)&a[4] = *(const float4*)&As[k][ty * 8 + 4];
            ulonglong2 b01 = *(const ulonglong2*)&Bs[k][tx * 8];
            ulonglong2 b23 = *(const ulonglong2*)&Bs[k][tx * 8 + 4];
            #pragma unroll
            for (int i = 0; i < 8; i++) {
                unsigned long long a2 = pack2(a[i], a[i]);
                fma2(acc2[i][0], a2, b01.x);
                fma2(acc2[i][1], a2, b01.y);
                fma2(acc2[i][2], a2, b23.x);
                fma2(acc2[i][3], a2, b23.y);
            }
        }
        __syncthreads();
    }

    #pragma unroll
    for (int i = 0; i < 8; i++) {
        int gr = row0 + ty * 8 + i;
        if (gr < M) {
            float v[8];
            #pragma unroll
            for (int j = 0; j < 4; j++) unpack2(acc2[i][j], v[2 * j], v[2 * j + 1]);
            *(float4*)&C[(size_t)gr * Ncols + col0 + tx * 8]     = *(float4*)&v[0];
            *(float4*)&C[(size_t)gr * Ncols + col0 + tx * 8 + 4] = *(float4*)&v[4];
        }
    }
}

// ---------------------------------------------------------------------------
// Node attention terms
// ---------------------------------------------------------------------------
__global__ void node_alpha1(const float* __restrict__ h,
                            const float* __restrict__ a_src,
                            const float* __restrict__ a_dst,
                            float* __restrict__ al_s,
                            float* __restrict__ al_d, int N) {
    int n = blockIdx.x;
    if (n >= N) return;
    int c = threadIdx.x;          // 0..127
    float v = h[n * 128 + c];
    float ps = v * a_src[c];
    float pd = v * a_dst[c];
    #pragma unroll
    for (int off = 16; off > 0; off >>= 1) {
        ps += __shfl_down_sync(0xFFFFFFFFu, ps, off);
        pd += __shfl_down_sync(0xFFFFFFFFu, pd, off);
    }
    if ((c & 31) == 0) {
        int hidx = c >> 5;
        al_s[n * 4 + hidx] = ps;
        al_d[n * 4 + hidx] = pd;
    }
}

__global__ void node_alpha2(const float* __restrict__ h,
                            const float* __restrict__ a_src,
                            const float* __restrict__ a_dst,
                            float* __restrict__ al_s,
                            float* __restrict__ al_d, int N) {
    int n = blockIdx.x;
    if (n >= N) return;
    int c = threadIdx.x;          // 0..255
    float v = h[n * 256 + c];
    float ps = v * a_src[c];
    float pd = v * a_dst[c];
    #pragma unroll
    for (int off = 16; off > 0; off >>= 1) {
        ps += __shfl_down_sync(0xFFFFFFFFu, ps, off);
        pd += __shfl_down_sync(0xFFFFFFFFu, pd, off);
    }
    __shared__ float ss[8], sd[8];
    if ((c & 31) == 0) { ss[c >> 5] = ps; sd[c >> 5] = pd; }
    __syncthreads();
    if (c == 0) {
        float a = 0.f, b = 0.f;
        #pragma unroll
        for (int i = 0; i < 8; i++) { a += ss[i]; b += sd[i]; }
        al_s[n] = a;
        al_d[n] = b;
    }
}

// ---------------------------------------------------------------------------
// Layer-1 gather aggregation + softmax + bias + relu. One warp per dst node.
// lane covers 4 channels; head = lane>>3.
// ---------------------------------------------------------------------------
__global__ __launch_bounds__(256)
void gather_agg1(const int* __restrict__ rowstart, const int* __restrict__ ssrc,
                 const float* __restrict__ als, const float* __restrict__ ald,
                 const float* __restrict__ hlin, const float* __restrict__ bias,
                 float* __restrict__ outp, int N) {
    int w = (blockIdx.x * blockDim.x + threadIdx.x) >> 5;
    int lane = threadIdx.x & 31;
    if (w >= N) return;
    const int d   = w;
    const int beg = rowstart[d];
    const int end = rowstart[d + 1];
    const float4 ad = *(const float4*)&ald[d * 4];

    // pass 1: softmax denominator (4 heads), edges strided across lanes
    float4 s = make_float4(0.f, 0.f, 0.f, 0.f);
    for (int j = beg + lane; j < end; j += 32) {
        int sn = ssrc[j];
        float4 as = *(const float4*)&als[sn * 4];
        s.x += __expf(lrelu(as.x + ad.x));
        s.y += __expf(lrelu(as.y + ad.y));
        s.z += __expf(lrelu(as.z + ad.z));
        s.w += __expf(lrelu(as.w + ad.w));
    }
    #pragma unroll
    for (int off = 16; off > 0; off >>= 1) {
        s.x += __shfl_xor_sync(0xFFFFFFFFu, s.x, off);
        s.y += __shfl_xor_sync(0xFFFFFFFFu, s.y, off);
        s.z += __shfl_xor_sync(0xFFFFFFFFu, s.z, off);
        s.w += __shfl_xor_sync(0xFFFFFFFFu, s.w, off);
    }
    const int head = lane >> 3;
    const float inv_h = 1.0f / (sel4(s, head) + 1e-16f);
    const float ad_h  = sel4(ad, head);

    // pass 2: weighted accumulate (whole warp per edge)
    float4 acc = make_float4(0.f, 0.f, 0.f, 0.f);
    for (int j = beg; j < end; j++) {
        int sn = ssrc[j];                                 // uniform across warp
        float alpha = __expf(lrelu(als[sn * 4 + head] + ad_h)) * inv_h;
        float4 v = *(const float4*)&hlin[sn * 128 + lane * 4];
        acc.x = fmaf(alpha, v.x, acc.x);
        acc.y = fmaf(alpha, v.y, acc.y);
        acc.z = fmaf(alpha, v.z, acc.z);
        acc.w = fmaf(alpha, v.w, acc.w);
    }
    float4 bb = *(const float4*)&bias[lane * 4];
    acc.x = fmaxf(acc.x + bb.x, 0.f);
    acc.y = fmaxf(acc.y + bb.y, 0.f);
    acc.z = fmaxf(acc.z + bb.z, 0.f);
    acc.w = fmaxf(acc.w + bb.w, 0.f);
    *(float4*)&outp[d * 128 + lane * 4] = acc;
}

// ---------------------------------------------------------------------------
// Layer-2 gather aggregation + softmax + bias. One warp per dst node.
// lane covers 8 channels (256 total).
// ---------------------------------------------------------------------------
__global__ __launch_bounds__(256)
void gather_agg2(const int* __restrict__ rowstart, const int* __restrict__ ssrc,
                 const float* __restrict__ als, const float* __restrict__ ald,
                 const float* __restrict__ hlin, const float* __restrict__ bias,
                 float* __restrict__ outp, int N) {
    int w = (blockIdx.x * blockDim.x + threadIdx.x) >> 5;
    int lane = threadIdx.x & 31;
    if (w >= N) return;
    const int d   = w;
    const int beg = rowstart[d];
    const int end = rowstart[d + 1];
    const float ad = ald[d];

    // pass 1: denominator
    float s = 0.f;
    for (int j = beg + lane; j < end; j += 32)
        s += __expf(lrelu(als[ssrc[j]] + ad));
    #pragma unroll
    for (int off = 16; off > 0; off >>= 1)
        s += __shfl_xor_sync(0xFFFFFFFFu, s, off);
    const float inv = 1.0f / (s + 1e-16f);

    // pass 2: accumulate 8 channels per lane
    float4 a0 = make_float4(0.f, 0.f, 0.f, 0.f);
    float4 a1 = make_float4(0.f, 0.f, 0.f, 0.f);
    for (int j = beg; j < end; j++) {
        int sn = ssrc[j];                                 // uniform across warp
        float alpha = __expf(lrelu(als[sn] + ad)) * inv;
        const float* hp = &hlin[sn * 256 + lane * 8];
        float4 v0 = *(const float4*)&hp[0];
        float4 v1 = *(const float4*)&hp[4];
        a0.x = fmaf(alpha, v0.x, a0.x);
        a0.y = fmaf(alpha, v0.y, a0.y);
        a0.z = fmaf(alpha, v0.z, a0.z);
        a0.w = fmaf(alpha, v0.w, a0.w);
        a1.x = fmaf(alpha, v1.x, a1.x);
        a1.y = fmaf(alpha, v1.y, a1.y);
        a1.z = fmaf(alpha, v1.z, a1.z);
        a1.w = fmaf(alpha, v1.w, a1.w);
    }
    float4 b0 = *(const float4*)&bias[lane * 8];
    float4 b1v = *(const float4*)&bias[lane * 8 + 4];
    a0.x += b0.x;  a0.y += b0.y;  a0.z += b0.z;  a0.w += b0.w;
    a1.x += b1v.x; a1.y += b1v.y; a1.z += b1v.z; a1.w += b1v.w;
    float* op = &outp[d * 256 + lane * 8];
    *(float4*)&op[0] = a0;
    *(float4*)&op[4] = a1;
}

// ---------------------------------------------------------------------------
// Launch
// ---------------------------------------------------------------------------
extern "C" void kernel_launch(void* const* d_in, const int* in_sizes, int n_in,
                              void* d_out, int out_size) {
    const float* x   = (const float*)d_in[0];
    const int*   ei  = (const int*)d_in[1];
    const float* W1  = (const float*)d_in[2];
    const float* as1 = (const float*)d_in[3];
    const float* ad1 = (const float*)d_in[4];
    const float* b1  = (const float*)d_in[5];
    const float* W2  = (const float*)d_in[6];
    const float* as2 = (const float*)d_in[7];
    const float* ad2 = (const float*)d_in[8];
    const float* b2  = (const float*)d_in[9];
    float* out = (float*)d_out;

    const int N    = in_sizes[0] / 128;   // 50000
    const int E    = in_sizes[1] / 2;     // 1600000
    const int Etot = E + N;               // 1650000

    float *hlin1, *als1p, *ald1p, *agg1, *hlin2, *als2p, *ald2p;
    int *cntp, *rowp, *curp, *ssrcp;
    cudaGetSymbolAddress((void**)&hlin1, g_hlin1);
    cudaGetSymbolAddress((void**)&als1p, g_als1);
    cudaGetSymbolAddress((void**)&ald1p, g_ald1);
    cudaGetSymbolAddress((void**)&agg1,  g_agg1);
    cudaGetSymbolAddress((void**)&hlin2, g_hlin2);
    cudaGetSymbolAddress((void**)&als2p, g_als2);
    cudaGetSymbolAddress((void**)&ald2p, g_ald2);
    cudaGetSymbolAddress((void**)&cntp,  g_count);
    cudaGetSymbolAddress((void**)&rowp,  g_rowstart);
    cudaGetSymbolAddress((void**)&curp,  g_cursor);
    cudaGetSymbolAddress((void**)&ssrcp, g_sorted_src);

    const int NW_BLOCKS = (N * 32 + 255) / 256;   // warp-per-node grids

    // --- CSR build (shared by both layers) ---
    zero_counts<<<(N + 255) / 256, 256>>>(cntp, N);
    hist_dst<<<(Etot + 255) / 256, 256>>>(ei, E, Etot, cntp);
    scan_counts<<<1, 1024>>>(cntp, rowp, curp, N);
    scatter_edges<<<(Etot + 255) / 256, 256>>>(ei, E, Etot, curp, ssrcp);

    // --- layer 1 ---
    {
        dim3 grid((N + 127) / 128, 1);
        sgemm_k128<<<grid, 256>>>(x, W1, hlin1, N, 128);
    }
    node_alpha1<<<N, 128>>>(hlin1, as1, ad1, als1p, ald1p, N);
    gather_agg1<<<NW_BLOCKS, 256>>>(rowp, ssrcp, als1p, ald1p, hlin1, b1, agg1, N);

    // --- layer 2 ---
    {
        dim3 grid((N + 127) / 128, 2);
        sgemm_k128<<<grid, 256>>>(agg1, W2, hlin2, N, 256);
    }
    node_alpha2<<<N, 256>>>(hlin2, as2, ad2, als2p, ald2p, N);
    gather_agg2<<<NW_BLOCKS, 256>>>(rowp, ssrcp, als2p, ald2p, hlin2, b2, out, N);
}

// round 4
// speedup vs baseline: 2.6910x; 1.1471x over previous
#include <cuda_runtime.h>
#include <cuda_fp16.h>

// ---------------------------------------------------------------------------
// GAT encoder: 2x GATConv (4 heads x 32, then 1 head x 256), ReLU between.
// N=50000 nodes, E=1.6M edges + N self-loops.
// R3: hlin1/hlin2 stored as fp16 (fp32 accumulate everywhere) -> halves the
//     dominant L2 gather traffic in gather_agg1/2. CSR gather, f32x2 SGEMM.
// ---------------------------------------------------------------------------

#define NNODES 50000
#define EMAX   1700000   // >= E + N

// Scratch (device globals; allocation inside kernel_launch is forbidden)
__device__ __align__(16) __half g_hlin1[NNODES * 128];  // x @ W1 (fp16)
__device__ __align__(16) float  g_als1[NNODES * 4];
__device__ __align__(16) float  g_ald1[NNODES * 4];
__device__ __align__(16) float  g_agg1[NNODES * 128];   // layer1 out (fp32, post bias+relu)
__device__ __align__(16) __half g_hlin2[NNODES * 256];  // h @ W2 (fp16)
__device__ __align__(16) float  g_als2[NNODES];
__device__ __align__(16) float  g_ald2[NNODES];
__device__ int g_count[NNODES];
__device__ int g_rowstart[NNODES + 1];
__device__ int g_cursor[NNODES];
__device__ int g_sorted_src[EMAX];

__device__ __forceinline__ float lrelu(float x) {
    return x > 0.0f ? x : 0.2f * x;
}

__device__ __forceinline__ unsigned long long pack2(float x, float y) {
    unsigned long long r;
    asm("mov.b64 %0, {%1, %2};" : "=l"(r) : "f"(x), "f"(y));
    return r;
}
__device__ __forceinline__ void fma2(unsigned long long& d,
                                     unsigned long long a, unsigned long long b) {
    asm("fma.rn.f32x2 %0, %1, %2, %0;" : "+l"(d) : "l"(a), "l"(b));
}
__device__ __forceinline__ void unpack2(unsigned long long v, float& lo, float& hi) {
    asm("mov.b64 {%0, %1}, %2;" : "=f"(lo), "=f"(hi) : "l"(v));
}
__device__ __forceinline__ float sel4(float4 v, int h) {
    float r = v.x;
    r = (h == 1) ? v.y : r;
    r = (h == 2) ? v.z : r;
    r = (h == 3) ? v.w : r;
    return r;
}

// ---------------------------------------------------------------------------
// CSR build
// ---------------------------------------------------------------------------
__global__ void zero_counts(int* __restrict__ cnt, int n) {
    int i = blockIdx.x * blockDim.x + threadIdx.x;
    if (i < n) cnt[i] = 0;
}

__global__ void hist_dst(const int* __restrict__ ei, int E, int Etot,
                         int* __restrict__ cnt) {
    int i = blockIdx.x * blockDim.x + threadIdx.x;
    if (i >= Etot) return;
    int d = (i < E) ? ei[E + i] : (i - E);
    atomicAdd(&cnt[d], 1);
}

__global__ __launch_bounds__(1024, 1)
void scan_counts(const int* __restrict__ cnt, int* __restrict__ rowstart,
                 int* __restrict__ cursor, int N) {
    __shared__ int wsum[32];
    __shared__ int s_carry;
    const int tid = threadIdx.x, lane = tid & 31, wid = tid >> 5;
    if (tid == 0) s_carry = 0;
    __syncthreads();
    for (int base = 0; base < N; base += 1024) {
        int i = base + tid;
        int v = (i < N) ? cnt[i] : 0;
        int x = v;
        #pragma unroll
        for (int off = 1; off < 32; off <<= 1) {
            int y = __shfl_up_sync(0xFFFFFFFFu, x, off);
            if (lane >= off) x += y;
        }
        if (lane == 31) wsum[wid] = x;
        __syncthreads();
        if (wid == 0) {
            int w = wsum[lane];
            #pragma unroll
            for (int off = 1; off < 32; off <<= 1) {
                int y = __shfl_up_sync(0xFFFFFFFFu, w, off);
                if (lane >= off) w += y;
            }
            wsum[lane] = w;
        }
        __syncthreads();
        int carry = s_carry;
        int excl = carry + (wid > 0 ? wsum[wid - 1] : 0) + x - v;
        if (i < N) { rowstart[i] = excl; cursor[i] = excl; }
        __syncthreads();
        if (tid == 1023) s_carry = carry + wsum[31];
        __syncthreads();
    }
    if (tid == 0) rowstart[N] = s_carry;
}

__global__ void scatter_edges(const int* __restrict__ ei, int E, int Etot,
                              int* __restrict__ cursor,
                              int* __restrict__ sorted_src) {
    int i = blockIdx.x * blockDim.x + threadIdx.x;
    if (i >= Etot) return;
    int s, d;
    if (i < E) { s = ei[i]; d = ei[E + i]; }
    else       { s = d = i - E; }
    int pos = atomicAdd(&cursor[d], 1);
    sorted_src[pos] = s;
}

// ---------------------------------------------------------------------------
// SGEMM: C_h[M,Ncols] (fp16) = A[M,128] @ B[128,Ncols]. fp32 accumulate,
// f32x2 packed FMA. 128x128 block tile, 8x8 per thread, 256 threads.
// ---------------------------------------------------------------------------
__global__ __launch_bounds__(256, 1)
void sgemm_k128_h(const float* __restrict__ A, const float* __restrict__ B,
                  __half* __restrict__ C, int M, int Ncols) {
    __shared__ float As[8][128];
    __shared__ float Bs[8][128];

    const int tid  = threadIdx.x;
    const int row0 = blockIdx.x * 128;
    const int col0 = blockIdx.y * 128;
    const int ty = tid >> 4;
    const int tx = tid & 15;

    const int lrow = tid >> 1;
    const int lkh  = (tid & 1) * 4;
    const int bk   = tid >> 5;
    const int bc   = (tid & 31) * 4;

    unsigned long long acc2[8][4];
    #pragma unroll
    for (int i = 0; i < 8; i++)
        #pragma unroll
        for (int j = 0; j < 4; j++) acc2[i][j] = 0ULL;

    for (int kc = 0; kc < 128; kc += 8) {
        float4 av = make_float4(0.f, 0.f, 0.f, 0.f);
        int gr = row0 + lrow;
        if (gr < M) av = *(const float4*)&A[(size_t)gr * 128 + kc + lkh];
        As[lkh + 0][lrow] = av.x;
        As[lkh + 1][lrow] = av.y;
        As[lkh + 2][lrow] = av.z;
        As[lkh + 3][lrow] = av.w;

        float4 bv = *(const float4*)&B[(size_t)(kc + bk) * Ncols + col0 + bc];
        *(float4*)&Bs[bk][bc] = bv;

        __syncthreads();

        #pragma unroll
        for (int k = 0; k < 8; k++) {
            float a[8];
            *(float4*)&a[0] = *(const float4*)&As[k][ty * 8];
            *(float4*)&a[4] = *(const float4*)&As[k][ty * 8 + 4];
            ulonglong2 b01 = *(const ulonglong2*)&Bs[k][tx * 8];
            ulonglong2 b23 = *(const ulonglong2*)&Bs[k][tx * 8 + 4];
            #pragma unroll
            for (int i = 0; i < 8; i++) {
                unsigned long long a2 = pack2(a[i], a[i]);
                fma2(acc2[i][0], a2, b01.x);
                fma2(acc2[i][1], a2, b01.y);
                fma2(acc2[i][2], a2, b23.x);
                fma2(acc2[i][3], a2, b23.y);
            }
        }
        __syncthreads();
    }

    #pragma unroll
    for (int i = 0; i < 8; i++) {
        int gr = row0 + ty * 8 + i;
        if (gr < M) {
            __half2 hv[4];
            #pragma unroll
            for (int j = 0; j < 4; j++) {
                float lo, hi;
                unpack2(acc2[i][j], lo, hi);
                hv[j] = __floats2half2_rn(lo, hi);
            }
            *(uint4*)&C[(size_t)gr * Ncols + col0 + tx * 8] = *(uint4*)hv;
        }
    }
}

// ---------------------------------------------------------------------------
// Node attention terms (read fp16 h)
// ---------------------------------------------------------------------------
__global__ void node_alpha1(const __half* __restrict__ h,
                            const float* __restrict__ a_src,
                            const float* __restrict__ a_dst,
                            float* __restrict__ al_s,
                            float* __restrict__ al_d, int N) {
    int n = blockIdx.x;
    if (n >= N) return;
    int c = threadIdx.x;          // 0..127
    float v = __half2float(h[n * 128 + c]);
    float ps = v * a_src[c];
    float pd = v * a_dst[c];
    #pragma unroll
    for (int off = 16; off > 0; off >>= 1) {
        ps += __shfl_down_sync(0xFFFFFFFFu, ps, off);
        pd += __shfl_down_sync(0xFFFFFFFFu, pd, off);
    }
    if ((c & 31) == 0) {
        int hidx = c >> 5;
        al_s[n * 4 + hidx] = ps;
        al_d[n * 4 + hidx] = pd;
    }
}

__global__ void node_alpha2(const __half* __restrict__ h,
                            const float* __restrict__ a_src,
                            const float* __restrict__ a_dst,
                            float* __restrict__ al_s,
                            float* __restrict__ al_d, int N) {
    int n = blockIdx.x;
    if (n >= N) return;
    int c = threadIdx.x;          // 0..255
    float v = __half2float(h[n * 256 + c]);
    float ps = v * a_src[c];
    float pd = v * a_dst[c];
    #pragma unroll
    for (int off = 16; off > 0; off >>= 1) {
        ps += __shfl_down_sync(0xFFFFFFFFu, ps, off);
        pd += __shfl_down_sync(0xFFFFFFFFu, pd, off);
    }
    __shared__ float ss[8], sd[8];
    if ((c & 31) == 0) { ss[c >> 5] = ps; sd[c >> 5] = pd; }
    __syncthreads();
    if (c == 0) {
        float a = 0.f, b = 0.f;
        #pragma unroll
        for (int i = 0; i < 8; i++) { a += ss[i]; b += sd[i]; }
        al_s[n] = a;
        al_d[n] = b;
    }
}

// ---------------------------------------------------------------------------
// Layer-1 gather aggregation + softmax + bias + relu. One warp per dst node.
// hlin in fp16; lane covers 4 channels; head = lane>>3. Output fp32.
// ---------------------------------------------------------------------------
__global__ __launch_bounds__(256)
void gather_agg1(const int* __restrict__ rowstart, const int* __restrict__ ssrc,
                 const float* __restrict__ als, const float* __restrict__ ald,
                 const __half* __restrict__ hlin, const float* __restrict__ bias,
                 float* __restrict__ outp, int N) {
    int w = (blockIdx.x * blockDim.x + threadIdx.x) >> 5;
    int lane = threadIdx.x & 31;
    if (w >= N) return;
    const int d   = w;
    const int beg = rowstart[d];
    const int end = rowstart[d + 1];
    const float4 ad = *(const float4*)&ald[d * 4];

    // pass 1: softmax denominator (4 heads), edges strided across lanes
    float4 s = make_float4(0.f, 0.f, 0.f, 0.f);
    for (int j = beg + lane; j < end; j += 32) {
        int sn = ssrc[j];
        float4 as = *(const float4*)&als[sn * 4];
        s.x += __expf(lrelu(as.x + ad.x));
        s.y += __expf(lrelu(as.y + ad.y));
        s.z += __expf(lrelu(as.z + ad.z));
        s.w += __expf(lrelu(as.w + ad.w));
    }
    #pragma unroll
    for (int off = 16; off > 0; off >>= 1) {
        s.x += __shfl_xor_sync(0xFFFFFFFFu, s.x, off);
        s.y += __shfl_xor_sync(0xFFFFFFFFu, s.y, off);
        s.z += __shfl_xor_sync(0xFFFFFFFFu, s.z, off);
        s.w += __shfl_xor_sync(0xFFFFFFFFu, s.w, off);
    }
    const int head = lane >> 3;
    const float inv_h = 1.0f / (sel4(s, head) + 1e-16f);
    const float ad_h  = sel4(ad, head);

    // pass 2: weighted accumulate (whole warp per edge), fp16 gather
    float4 acc = make_float4(0.f, 0.f, 0.f, 0.f);
    for (int j = beg; j < end; j++) {
        int sn = ssrc[j];                                 // uniform across warp
        float alpha = __expf(lrelu(als[sn * 4 + head] + ad_h)) * inv_h;
        const __half2* hp = (const __half2*)&hlin[sn * 128 + lane * 4];
        uint2 raw = *(const uint2*)hp;                    // 4 halves
        float2 f0 = __half22float2(*(const __half2*)&raw.x);
        float2 f1 = __half22float2(*(const __half2*)&raw.y);
        acc.x = fmaf(alpha, f0.x, acc.x);
        acc.y = fmaf(alpha, f0.y, acc.y);
        acc.z = fmaf(alpha, f1.x, acc.z);
        acc.w = fmaf(alpha, f1.y, acc.w);
    }
    float4 bb = *(const float4*)&bias[lane * 4];
    acc.x = fmaxf(acc.x + bb.x, 0.f);
    acc.y = fmaxf(acc.y + bb.y, 0.f);
    acc.z = fmaxf(acc.z + bb.z, 0.f);
    acc.w = fmaxf(acc.w + bb.w, 0.f);
    *(float4*)&outp[d * 128 + lane * 4] = acc;
}

// ---------------------------------------------------------------------------
// Layer-2 gather aggregation + softmax + bias. One warp per dst node.
// hlin in fp16; lane covers 8 channels (256 total). Output fp32.
// ---------------------------------------------------------------------------
__global__ __launch_bounds__(256)
void gather_agg2(const int* __restrict__ rowstart, const int* __restrict__ ssrc,
                 const float* __restrict__ als, const float* __restrict__ ald,
                 const __half* __restrict__ hlin, const float* __restrict__ bias,
                 float* __restrict__ outp, int N) {
    int w = (blockIdx.x * blockDim.x + threadIdx.x) >> 5;
    int lane = threadIdx.x & 31;
    if (w >= N) return;
    const int d   = w;
    const int beg = rowstart[d];
    const int end = rowstart[d + 1];
    const float ad = ald[d];

    // pass 1: denominator
    float s = 0.f;
    for (int j = beg + lane; j < end; j += 32)
        s += __expf(lrelu(als[ssrc[j]] + ad));
    #pragma unroll
    for (int off = 16; off > 0; off >>= 1)
        s += __shfl_xor_sync(0xFFFFFFFFu, s, off);
    const float inv = 1.0f / (s + 1e-16f);

    // pass 2: accumulate 8 channels per lane, fp16 gather (16 B/lane)
    float4 a0 = make_float4(0.f, 0.f, 0.f, 0.f);
    float4 a1 = make_float4(0.f, 0.f, 0.f, 0.f);
    for (int j = beg; j < end; j++) {
        int sn = ssrc[j];                                 // uniform across warp
        float alpha = __expf(lrelu(als[sn] + ad)) * inv;
        uint4 raw = *(const uint4*)&hlin[sn * 256 + lane * 8];  // 8 halves
        float2 f0 = __half22float2(*(const __half2*)&raw.x);
        float2 f1 = __half22float2(*(const __half2*)&raw.y);
        float2 f2 = __half22float2(*(const __half2*)&raw.z);
        float2 f3 = __half22float2(*(const __half2*)&raw.w);
        a0.x = fmaf(alpha, f0.x, a0.x);
        a0.y = fmaf(alpha, f0.y, a0.y);
        a0.z = fmaf(alpha, f1.x, a0.z);
        a0.w = fmaf(alpha, f1.y, a0.w);
        a1.x = fmaf(alpha, f2.x, a1.x);
        a1.y = fmaf(alpha, f2.y, a1.y);
        a1.z = fmaf(alpha, f3.x, a1.z);
        a1.w = fmaf(alpha, f3.y, a1.w);
    }
    float4 b0 = *(const float4*)&bias[lane * 8];
    float4 b1v = *(const float4*)&bias[lane * 8 + 4];
    a0.x += b0.x;  a0.y += b0.y;  a0.z += b0.z;  a0.w += b0.w;
    a1.x += b1v.x; a1.y += b1v.y; a1.z += b1v.z; a1.w += b1v.w;
    float* op = &outp[d * 256 + lane * 8];
    *(float4*)&op[0] = a0;
    *(float4*)&op[4] = a1;
}

// ---------------------------------------------------------------------------
// Launch
// ---------------------------------------------------------------------------
extern "C" void kernel_launch(void* const* d_in, const int* in_sizes, int n_in,
                              void* d_out, int out_size) {
    const float* x   = (const float*)d_in[0];
    const int*   ei  = (const int*)d_in[1];
    const float* W1  = (const float*)d_in[2];
    const float* as1 = (const float*)d_in[3];
    const float* ad1 = (const float*)d_in[4];
    const float* b1  = (const float*)d_in[5];
    const float* W2  = (const float*)d_in[6];
    const float* as2 = (const float*)d_in[7];
    const float* ad2 = (const float*)d_in[8];
    const float* b2  = (const float*)d_in[9];
    float* out = (float*)d_out;

    const int N    = in_sizes[0] / 128;   // 50000
    const int E    = in_sizes[1] / 2;     // 1600000
    const int Etot = E + N;               // 1650000

    float *als1p, *ald1p, *agg1, *als2p, *ald2p;
    __half *hlin1, *hlin2;
    int *cntp, *rowp, *curp, *ssrcp;
    cudaGetSymbolAddress((void**)&hlin1, g_hlin1);
    cudaGetSymbolAddress((void**)&als1p, g_als1);
    cudaGetSymbolAddress((void**)&ald1p, g_ald1);
    cudaGetSymbolAddress((void**)&agg1,  g_agg1);
    cudaGetSymbolAddress((void**)&hlin2, g_hlin2);
    cudaGetSymbolAddress((void**)&als2p, g_als2);
    cudaGetSymbolAddress((void**)&ald2p, g_ald2);
    cudaGetSymbolAddress((void**)&cntp,  g_count);
    cudaGetSymbolAddress((void**)&rowp,  g_rowstart);
    cudaGetSymbolAddress((void**)&curp,  g_cursor);
    cudaGetSymbolAddress((void**)&ssrcp, g_sorted_src);

    const int NW_BLOCKS = (N * 32 + 255) / 256;

    // --- CSR build (shared by both layers) ---
    zero_counts<<<(N + 255) / 256, 256>>>(cntp, N);
    hist_dst<<<(Etot + 255) / 256, 256>>>(ei, E, Etot, cntp);
    scan_counts<<<1, 1024>>>(cntp, rowp, curp, N);
    scatter_edges<<<(Etot + 255) / 256, 256>>>(ei, E, Etot, curp, ssrcp);

    // --- layer 1 ---
    {
        dim3 grid((N + 127) / 128, 1);
        sgemm_k128_h<<<grid, 256>>>(x, W1, hlin1, N, 128);
    }
    node_alpha1<<<N, 128>>>(hlin1, as1, ad1, als1p, ald1p, N);
    gather_agg1<<<NW_BLOCKS, 256>>>(rowp, ssrcp, als1p, ald1p, hlin1, b1, agg1, N);

    // --- layer 2 ---
    {
        dim3 grid((N + 127) / 128, 2);
        sgemm_k128_h<<<grid, 256>>>(agg1, W2, hlin2, N, 256);
    }
    node_alpha2<<<N, 256>>>(hlin2, as2, ad2, als2p, ald2p, N);
    gather_agg2<<<NW_BLOCKS, 256>>>(rowp, ssrcp, als2p, ald2p, hlin2, b2, out, N);
}

// round 5
// speedup vs baseline: 3.2270x; 1.1992x over previous
#include <cuda_runtime.h>
#include <cuda_fp16.h>

// ---------------------------------------------------------------------------
// GAT encoder: 2x GATConv (4 heads x 32, then 1 head x 256), ReLU between.
// N=50000 nodes, E=1.6M edges + N self-loops.
// R4: HMMA tensor-core GEMMs (m16n8k16 fp16 in / fp32 acc). All hidden
//     activations fp16; fp32 accumulation everywhere else. CSR gather.
// ---------------------------------------------------------------------------

#define NNODES 50000
#define EMAX   1700000   // >= E + N

// Scratch (device globals; allocation inside kernel_launch is forbidden)
__device__ __align__(16) __half g_xh[NNODES * 128];     // x in fp16
__device__ __align__(16) __half g_wt1h[128 * 128];      // W1^T fp16  [n][k]
__device__ __align__(16) __half g_wt2h[256 * 128];      // W2^T fp16  [n][k]
__device__ __align__(16) __half g_hlin1[NNODES * 128];  // x @ W1 (fp16)
__device__ __align__(16) float  g_als1[NNODES * 4];
__device__ __align__(16) float  g_ald1[NNODES * 4];
__device__ __align__(16) __half g_agg1h[NNODES * 128];  // layer1 out (fp16)
__device__ __align__(16) __half g_hlin2[NNODES * 256];  // h @ W2 (fp16)
__device__ __align__(16) float  g_als2[NNODES];
__device__ __align__(16) float  g_ald2[NNODES];
__device__ int g_count[NNODES];
__device__ int g_rowstart[NNODES + 1];
__device__ int g_cursor[NNODES];
__device__ int g_sorted_src[EMAX];

__device__ __forceinline__ float lrelu(float x) {
    return x > 0.0f ? x : 0.2f * x;
}
__device__ __forceinline__ float sel4(float4 v, int h) {
    float r = v.x;
    r = (h == 1) ? v.y : r;
    r = (h == 2) ? v.z : r;
    r = (h == 3) ? v.w : r;
    return r;
}

// ---------------------------------------------------------------------------
// Conversions
// ---------------------------------------------------------------------------
__global__ void cvt_f2h(const float* __restrict__ in, __half* __restrict__ out, int n4) {
    int i = blockIdx.x * blockDim.x + threadIdx.x;
    if (i >= n4) return;
    float4 v = *(const float4*)&in[i * 4];
    __half2 h0 = __floats2half2_rn(v.x, v.y);
    __half2 h1 = __floats2half2_rn(v.z, v.w);
    uint2 u;
    u.x = *(unsigned int*)&h0;
    u.y = *(unsigned int*)&h1;
    *(uint2*)&out[i * 4] = u;
}

// WT[n][k] = W[k][n] in fp16.  W is [K][Ncols] row-major. K=128.
__global__ void cvt_wt(const float* __restrict__ W, __half* __restrict__ WT, int Ncols) {
    int i = blockIdx.x * blockDim.x + threadIdx.x;
    int total = 128 * Ncols;
    if (i >= total) return;
    int n = i >> 7;         // i / 128
    int k = i & 127;        // i % 128
    WT[i] = __float2half(W[k * Ncols + n]);
}

// ---------------------------------------------------------------------------
// CSR build
// ---------------------------------------------------------------------------
__global__ void zero_counts(int* __restrict__ cnt, int n) {
    int i = blockIdx.x * blockDim.x + threadIdx.x;
    if (i < n) cnt[i] = 0;
}

__global__ void hist_dst(const int* __restrict__ ei, int E, int Etot,
                         int* __restrict__ cnt) {
    int i = blockIdx.x * blockDim.x + threadIdx.x;
    if (i >= Etot) return;
    int d = (i < E) ? ei[E + i] : (i - E);
    atomicAdd(&cnt[d], 1);
}

__global__ __launch_bounds__(1024, 1)
void scan_counts(const int* __restrict__ cnt, int* __restrict__ rowstart,
                 int* __restrict__ cursor, int N) {
    __shared__ int wsum[32];
    __shared__ int s_carry;
    const int tid = threadIdx.x, lane = tid & 31, wid = tid >> 5;
    if (tid == 0) s_carry = 0;
    __syncthreads();
    for (int base = 0; base < N; base += 1024) {
        int i = base + tid;
        int v = (i < N) ? cnt[i] : 0;
        int x = v;
        #pragma unroll
        for (int off = 1; off < 32; off <<= 1) {
            int y = __shfl_up_sync(0xFFFFFFFFu, x, off);
            if (lane >= off) x += y;
        }
        if (lane == 31) wsum[wid] = x;
        __syncthreads();
        if (wid == 0) {
            int w = wsum[lane];
            #pragma unroll
            for (int off = 1; off < 32; off <<= 1) {
                int y = __shfl_up_sync(0xFFFFFFFFu, w, off);
                if (lane >= off) w += y;
            }
            wsum[lane] = w;
        }
        __syncthreads();
        int carry = s_carry;
        int excl = carry + (wid > 0 ? wsum[wid - 1] : 0) + x - v;
        if (i < N) { rowstart[i] = excl; cursor[i] = excl; }
        __syncthreads();
        if (tid == 1023) s_carry = carry + wsum[31];
        __syncthreads();
    }
    if (tid == 0) rowstart[N] = s_carry;
}

__global__ void scatter_edges(const int* __restrict__ ei, int E, int Etot,
                              int* __restrict__ cursor,
                              int* __restrict__ sorted_src) {
    int i = blockIdx.x * blockDim.x + threadIdx.x;
    if (i >= Etot) return;
    int s, d;
    if (i < E) { s = ei[i]; d = ei[E + i]; }
    else       { s = d = i - E; }
    int pos = atomicAdd(&cursor[d], 1);
    sorted_src[pos] = s;
}

// ---------------------------------------------------------------------------
// HGEMM: C_h[M,Ncols] = A_h[M,128] @ W (given as WT[n][k], fp16), fp32 acc.
// mma.sync m16n8k16. Block tile 128x64, 8 warps (4M x 2N), warp tile 32x32.
// ---------------------------------------------------------------------------
#define AS_STRIDE 40    // halves per A smem row (32 data + 8 pad)
#define BS_STRIDE 136   // halves per B smem row (128 data + 8 pad)

__device__ __forceinline__ void mma16816(float* c, const unsigned int* a,
                                         unsigned int b0, unsigned int b1) {
    asm volatile(
        "mma.sync.aligned.m16n8k16.row.col.f32.f16.f16.f32 "
        "{%0,%1,%2,%3}, {%4,%5,%6,%7}, {%8,%9}, {%0,%1,%2,%3};"
        : "+f"(c[0]), "+f"(c[1]), "+f"(c[2]), "+f"(c[3])
        : "r"(a[0]), "r"(a[1]), "r"(a[2]), "r"(a[3]), "r"(b0), "r"(b1));
}

__global__ __launch_bounds__(256, 1)
void hgemm_k128(const __half* __restrict__ A, const __half* __restrict__ WT,
                __half* __restrict__ C, int M, int Ncols) {
    __shared__ __half As[128 * AS_STRIDE];
    __shared__ __half Bs[64 * BS_STRIDE];

    const int tid  = threadIdx.x;
    const int lane = tid & 31;
    const int wid  = tid >> 5;
    const int row0 = blockIdx.x * 128;
    const int col0 = blockIdx.y * 64;
    const int wm = (wid & 3) * 32;     // warp M offset
    const int wn = (wid >> 2) * 32;    // warp N offset

    // Load full W^T block: rows col0..col0+63, 128 k halves each.
    {
        int n = tid >> 2;
        int p = (tid & 3) * 32;
        const uint4* src = (const uint4*)&WT[(size_t)(col0 + n) * 128 + p];
        uint4* dst = (uint4*)&Bs[n * BS_STRIDE + p];
        dst[0] = src[0]; dst[1] = src[1]; dst[2] = src[2]; dst[3] = src[3];
    }

    float acc[2][4][4];
    #pragma unroll
    for (int mt = 0; mt < 2; mt++)
        #pragma unroll
        for (int nt = 0; nt < 4; nt++)
            #pragma unroll
            for (int q = 0; q < 4; q++) acc[mt][nt][q] = 0.0f;

    const int arow = tid >> 1;
    const int acol = (tid & 1) * 16;
    const int frow = lane >> 2;        // 0..7
    const int fcol = 2 * (lane & 3);   // 0,2,4,6

    for (int kc = 0; kc < 128; kc += 32) {
        uint4 v0 = make_uint4(0, 0, 0, 0), v1 = make_uint4(0, 0, 0, 0);
        int gr = row0 + arow;
        if (gr < M) {
            const uint4* s = (const uint4*)&A[(size_t)gr * 128 + kc + acol];
            v0 = s[0]; v1 = s[1];
        }
        __syncthreads();   // previous iter's frag reads done (also covers Bs, iter 0)
        *(uint4*)&As[arow * AS_STRIDE + acol]     = v0;
        *(uint4*)&As[arow * AS_STRIDE + acol + 8] = v1;
        __syncthreads();

        #pragma unroll
        for (int kk = 0; kk < 32; kk += 16) {
            unsigned int a[2][4];
            #pragma unroll
            for (int mt = 0; mt < 2; mt++) {
                int r = wm + mt * 16 + frow;
                int c = kk + fcol;
                a[mt][0] = *(const unsigned int*)&As[r * AS_STRIDE + c];
                a[mt][1] = *(const unsigned int*)&As[(r + 8) * AS_STRIDE + c];
                a[mt][2] = *(const unsigned int*)&As[r * AS_STRIDE + c + 8];
                a[mt][3] = *(const unsigned int*)&As[(r + 8) * AS_STRIDE + c + 8];
            }
            #pragma unroll
            for (int nt = 0; nt < 4; nt++) {
                int n = wn + nt * 8 + frow;
                int ck = kc + kk + fcol;
                unsigned int b0 = *(const unsigned int*)&Bs[n * BS_STRIDE + ck];
                unsigned int b1 = *(const unsigned int*)&Bs[n * BS_STRIDE + ck + 8];
                mma16816(acc[0][nt], a[0], b0, b1);
                mma16816(acc[1][nt], a[1], b0, b1);
            }
        }
    }

    #pragma unroll
    for (int mt = 0; mt < 2; mt++) {
        int r = row0 + wm + mt * 16 + frow;
        #pragma unroll
        for (int nt = 0; nt < 4; nt++) {
            int c = col0 + wn + nt * 8 + fcol;
            if (r < M) {
                __half2 h = __floats2half2_rn(acc[mt][nt][0], acc[mt][nt][1]);
                *(__half2*)&C[(size_t)r * Ncols + c] = h;
            }
            if (r + 8 < M) {
                __half2 h = __floats2half2_rn(acc[mt][nt][2], acc[mt][nt][3]);
                *(__half2*)&C[(size_t)(r + 8) * Ncols + c] = h;
            }
        }
    }
}

// ---------------------------------------------------------------------------
// Node attention terms (read fp16 h)
// ---------------------------------------------------------------------------
__global__ void node_alpha1(const __half* __restrict__ h,
                            const float* __restrict__ a_src,
                            const float* __restrict__ a_dst,
                            float* __restrict__ al_s,
                            float* __restrict__ al_d, int N) {
    int n = blockIdx.x;
    if (n >= N) return;
    int c = threadIdx.x;          // 0..127
    float v = __half2float(h[n * 128 + c]);
    float ps = v * a_src[c];
    float pd = v * a_dst[c];
    #pragma unroll
    for (int off = 16; off > 0; off >>= 1) {
        ps += __shfl_down_sync(0xFFFFFFFFu, ps, off);
        pd += __shfl_down_sync(0xFFFFFFFFu, pd, off);
    }
    if ((c & 31) == 0) {
        int hidx = c >> 5;
        al_s[n * 4 + hidx] = ps;
        al_d[n * 4 + hidx] = pd;
    }
}

__global__ void node_alpha2(const __half* __restrict__ h,
                            const float* __restrict__ a_src,
                            const float* __restrict__ a_dst,
                            float* __restrict__ al_s,
                            float* __restrict__ al_d, int N) {
    int n = blockIdx.x;
    if (n >= N) return;
    int c = threadIdx.x;          // 0..255
    float v = __half2float(h[n * 256 + c]);
    float ps = v * a_src[c];
    float pd = v * a_dst[c];
    #pragma unroll
    for (int off = 16; off > 0; off >>= 1) {
        ps += __shfl_down_sync(0xFFFFFFFFu, ps, off);
        pd += __shfl_down_sync(0xFFFFFFFFu, pd, off);
    }
    __shared__ float ss[8], sd[8];
    if ((c & 31) == 0) { ss[c >> 5] = ps; sd[c >> 5] = pd; }
    __syncthreads();
    if (c == 0) {
        float a = 0.f, b = 0.f;
        #pragma unroll
        for (int i = 0; i < 8; i++) { a += ss[i]; b += sd[i]; }
        al_s[n] = a;
        al_d[n] = b;
    }
}

// ---------------------------------------------------------------------------
// Layer-1 gather aggregation + softmax + bias + relu. Warp per dst node.
// fp16 gather, fp32 accumulate, fp16 output (feeds GEMM2).
// ---------------------------------------------------------------------------
__global__ __launch_bounds__(256)
void gather_agg1(const int* __restrict__ rowstart, const int* __restrict__ ssrc,
                 const float* __restrict__ als, const float* __restrict__ ald,
                 const __half* __restrict__ hlin, const float* __restrict__ bias,
                 __half* __restrict__ outp, int N) {
    int w = (blockIdx.x * blockDim.x + threadIdx.x) >> 5;
    int lane = threadIdx.x & 31;
    if (w >= N) return;
    const int d   = w;
    const int beg = rowstart[d];
    const int end = rowstart[d + 1];
    const float4 ad = *(const float4*)&ald[d * 4];

    float4 s = make_float4(0.f, 0.f, 0.f, 0.f);
    for (int j = beg + lane; j < end; j += 32) {
        int sn = ssrc[j];
        float4 as = *(const float4*)&als[sn * 4];
        s.x += __expf(lrelu(as.x + ad.x));
        s.y += __expf(lrelu(as.y + ad.y));
        s.z += __expf(lrelu(as.z + ad.z));
        s.w += __expf(lrelu(as.w + ad.w));
    }
    #pragma unroll
    for (int off = 16; off > 0; off >>= 1) {
        s.x += __shfl_xor_sync(0xFFFFFFFFu, s.x, off);
        s.y += __shfl_xor_sync(0xFFFFFFFFu, s.y, off);
        s.z += __shfl_xor_sync(0xFFFFFFFFu, s.z, off);
        s.w += __shfl_xor_sync(0xFFFFFFFFu, s.w, off);
    }
    const int head = lane >> 3;
    const float inv_h = 1.0f / (sel4(s, head) + 1e-16f);
    const float ad_h  = sel4(ad, head);

    float4 acc = make_float4(0.f, 0.f, 0.f, 0.f);
    for (int j = beg; j < end; j++) {
        int sn = ssrc[j];
        float alpha = __expf(lrelu(als[sn * 4 + head] + ad_h)) * inv_h;
        uint2 raw = *(const uint2*)&hlin[sn * 128 + lane * 4];
        float2 f0 = __half22float2(*(const __half2*)&raw.x);
        float2 f1 = __half22float2(*(const __half2*)&raw.y);
        acc.x = fmaf(alpha, f0.x, acc.x);
        acc.y = fmaf(alpha, f0.y, acc.y);
        acc.z = fmaf(alpha, f1.x, acc.z);
        acc.w = fmaf(alpha, f1.y, acc.w);
    }
    float4 bb = *(const float4*)&bias[lane * 4];
    acc.x = fmaxf(acc.x + bb.x, 0.f);
    acc.y = fmaxf(acc.y + bb.y, 0.f);
    acc.z = fmaxf(acc.z + bb.z, 0.f);
    acc.w = fmaxf(acc.w + bb.w, 0.f);
    __half2 h0 = __floats2half2_rn(acc.x, acc.y);
    __half2 h1 = __floats2half2_rn(acc.z, acc.w);
    uint2 u;
    u.x = *(unsigned int*)&h0;
    u.y = *(unsigned int*)&h1;
    *(uint2*)&outp[d * 128 + lane * 4] = u;
}

// ---------------------------------------------------------------------------
// Layer-2 gather aggregation + softmax + bias. Warp per dst node. fp32 out.
// ---------------------------------------------------------------------------
__global__ __launch_bounds__(256)
void gather_agg2(const int* __restrict__ rowstart, const int* __restrict__ ssrc,
                 const float* __restrict__ als, const float* __restrict__ ald,
                 const __half* __restrict__ hlin, const float* __restrict__ bias,
                 float* __restrict__ outp, int N) {
    int w = (blockIdx.x * blockDim.x + threadIdx.x) >> 5;
    int lane = threadIdx.x & 31;
    if (w >= N) return;
    const int d   = w;
    const int beg = rowstart[d];
    const int end = rowstart[d + 1];
    const float ad = ald[d];

    float s = 0.f;
    for (int j = beg + lane; j < end; j += 32)
        s += __expf(lrelu(als[ssrc[j]] + ad));
    #pragma unroll
    for (int off = 16; off > 0; off >>= 1)
        s += __shfl_xor_sync(0xFFFFFFFFu, s, off);
    const float inv = 1.0f / (s + 1e-16f);

    float4 a0 = make_float4(0.f, 0.f, 0.f, 0.f);
    float4 a1 = make_float4(0.f, 0.f, 0.f, 0.f);
    for (int j = beg; j < end; j++) {
        int sn = ssrc[j];
        float alpha = __expf(lrelu(als[sn] + ad)) * inv;
        uint4 raw = *(const uint4*)&hlin[sn * 256 + lane * 8];
        float2 f0 = __half22float2(*(const __half2*)&raw.x);
        float2 f1 = __half22float2(*(const __half2*)&raw.y);
        float2 f2 = __half22float2(*(const __half2*)&raw.z);
        float2 f3 = __half22float2(*(const __half2*)&raw.w);
        a0.x = fmaf(alpha, f0.x, a0.x);
        a0.y = fmaf(alpha, f0.y, a0.y);
        a0.z = fmaf(alpha, f1.x, a0.z);
        a0.w = fmaf(alpha, f1.y, a0.w);
        a1.x = fmaf(alpha, f2.x, a1.x);
        a1.y = fmaf(alpha, f2.y, a1.y);
        a1.z = fmaf(alpha, f3.x, a1.z);
        a1.w = fmaf(alpha, f3.y, a1.w);
    }
    float4 b0 = *(const float4*)&bias[lane * 8];
    float4 b1v = *(const float4*)&bias[lane * 8 + 4];
    a0.x += b0.x;  a0.y += b0.y;  a0.z += b0.z;  a0.w += b0.w;
    a1.x += b1v.x; a1.y += b1v.y; a1.z += b1v.z; a1.w += b1v.w;
    float* op = &outp[d * 256 + lane * 8];
    *(float4*)&op[0] = a0;
    *(float4*)&op[4] = a1;
}

// ---------------------------------------------------------------------------
// Launch
// ---------------------------------------------------------------------------
extern "C" void kernel_launch(void* const* d_in, const int* in_sizes, int n_in,
                              void* d_out, int out_size) {
    const float* x   = (const float*)d_in[0];
    const int*   ei  = (const int*)d_in[1];
    const float* W1  = (const float*)d_in[2];
    const float* as1 = (const float*)d_in[3];
    const float* ad1 = (const float*)d_in[4];
    const float* b1  = (const float*)d_in[5];
    const float* W2  = (const float*)d_in[6];
    const float* as2 = (const float*)d_in[7];
    const float* ad2 = (const float*)d_in[8];
    const float* b2  = (const float*)d_in[9];
    float* out = (float*)d_out;

    const int N    = in_sizes[0] / 128;   // 50000
    const int E    = in_sizes[1] / 2;     // 1600000
    const int Etot = E + N;               // 1650000

    float *als1p, *ald1p, *als2p, *ald2p;
    __half *xh, *wt1h, *wt2h, *hlin1, *agg1h, *hlin2;
    int *cntp, *rowp, *curp, *ssrcp;
    cudaGetSymbolAddress((void**)&xh,    g_xh);
    cudaGetSymbolAddress((void**)&wt1h,  g_wt1h);
    cudaGetSymbolAddress((void**)&wt2h,  g_wt2h);
    cudaGetSymbolAddress((void**)&hlin1, g_hlin1);
    cudaGetSymbolAddress((void**)&als1p, g_als1);
    cudaGetSymbolAddress((void**)&ald1p, g_ald1);
    cudaGetSymbolAddress((void**)&agg1h, g_agg1h);
    cudaGetSymbolAddress((void**)&hlin2, g_hlin2);
    cudaGetSymbolAddress((void**)&als2p, g_als2);
    cudaGetSymbolAddress((void**)&ald2p, g_ald2);
    cudaGetSymbolAddress((void**)&cntp,  g_count);
    cudaGetSymbolAddress((void**)&rowp,  g_rowstart);
    cudaGetSymbolAddress((void**)&curp,  g_cursor);
    cudaGetSymbolAddress((void**)&ssrcp, g_sorted_src);

    const int NW_BLOCKS = (N * 32 + 255) / 256;

    // --- conversions ---
    cvt_f2h<<<(N * 128 / 4 + 255) / 256, 256>>>(x, xh, N * 128 / 4);
    cvt_wt<<<(128 * 128 + 255) / 256, 256>>>(W1, wt1h, 128);
    cvt_wt<<<(128 * 256 + 255) / 256, 256>>>(W2, wt2h, 256);

    // --- CSR build (shared by both layers) ---
    zero_counts<<<(N + 255) / 256, 256>>>(cntp, N);
    hist_dst<<<(Etot + 255) / 256, 256>>>(ei, E, Etot, cntp);
    scan_counts<<<1, 1024>>>(cntp, rowp, curp, N);
    scatter_edges<<<(Etot + 255) / 256, 256>>>(ei, E, Etot, curp, ssrcp);

    // --- layer 1 ---
    {
        dim3 grid((N + 127) / 128, 2);   // Ncols=128 -> 2 x 64
        hgemm_k128<<<grid, 256>>>(xh, wt1h, hlin1, N, 128);
    }
    node_alpha1<<<N, 128>>>(hlin1, as1, ad1, als1p, ald1p, N);
    gather_agg1<<<NW_BLOCKS, 256>>>(rowp, ssrcp, als1p, ald1p, hlin1, b1, agg1h, N);

    // --- layer 2 ---
    {
        dim3 grid((N + 127) / 128, 4);   // Ncols=256 -> 4 x 64
        hgemm_k128<<<grid, 256>>>(agg1h, wt2h, hlin2, N, 256);
    }
    node_alpha2<<<N, 256>>>(hlin2, as2, ad2, als2p, ald2p, N);
    gather_agg2<<<NW_BLOCKS, 256>>>(rowp, ssrcp, als2p, ald2p, hlin2, b2, out, N);
}

// round 6
// speedup vs baseline: 3.7769x; 1.1704x over previous
#include <cuda_runtime.h>
#include <cuda_fp16.h>

// ---------------------------------------------------------------------------
// GAT encoder: 2x GATConv (4 heads x 32, then 1 head x 256), ReLU between.
// N=50000 nodes, E=1.6M edges + N self-loops.
// R5: single-pass fused gather (sum(e*v)/sum(e)), software-pipelined edge
//     loop, warp-per-node alpha kernels, faster CSR build. HMMA GEMMs.
// ---------------------------------------------------------------------------

#define NNODES 50000
#define EMAX   1700000   // >= E + N

__device__ __align__(16) __half g_xh[NNODES * 128];
__device__ __align__(16) __half g_wt1h[128 * 128];
__device__ __align__(16) __half g_wt2h[256 * 128];
__device__ __align__(16) __half g_hlin1[NNODES * 128];
__device__ __align__(16) float  g_als1[NNODES * 4];
__device__ __align__(16) float  g_ald1[NNODES * 4];
__device__ __align__(16) __half g_agg1h[NNODES * 128];
__device__ __align__(16) __half g_hlin2[NNODES * 256];
__device__ __align__(16) float  g_als2[NNODES];
__device__ __align__(16) float  g_ald2[NNODES];
__device__ int g_count[NNODES];
__device__ int g_rowstart[NNODES + 1];
__device__ int g_cursor[NNODES];
__device__ int g_sorted_src[EMAX];

__device__ __forceinline__ float lrelu(float x) {
    return x > 0.0f ? x : 0.2f * x;
}
__device__ __forceinline__ float sel4(float4 v, int h) {
    float r = v.x;
    r = (h == 1) ? v.y : r;
    r = (h == 2) ? v.z : r;
    r = (h == 3) ? v.w : r;
    return r;
}

// ---------------------------------------------------------------------------
// Conversions
// ---------------------------------------------------------------------------
__global__ void cvt_f2h(const float* __restrict__ in, __half* __restrict__ out, int n4) {
    int i = blockIdx.x * blockDim.x + threadIdx.x;
    if (i >= n4) return;
    float4 v = *(const float4*)&in[i * 4];
    __half2 h0 = __floats2half2_rn(v.x, v.y);
    __half2 h1 = __floats2half2_rn(v.z, v.w);
    uint2 u;
    u.x = *(unsigned int*)&h0;
    u.y = *(unsigned int*)&h1;
    *(uint2*)&out[i * 4] = u;
}

__global__ void cvt_wt(const float* __restrict__ W, __half* __restrict__ WT, int Ncols) {
    int i = blockIdx.x * blockDim.x + threadIdx.x;
    int total = 128 * Ncols;
    if (i >= total) return;
    int n = i >> 7;
    int k = i & 127;
    WT[i] = __float2half(W[k * Ncols + n]);
}

// ---------------------------------------------------------------------------
// CSR build
// ---------------------------------------------------------------------------
__global__ void hist_dst(const int* __restrict__ ei, int E, int Etot,
                         int* __restrict__ cnt) {
    int stride = gridDim.x * blockDim.x;
    for (int i = blockIdx.x * blockDim.x + threadIdx.x; i < Etot; i += stride) {
        int d = (i < E) ? ei[E + i] : (i - E);
        atomicAdd(&cnt[d], 1);
    }
}

// 4 elements per thread per iteration; N assumed multiple of 4 (guarded).
__global__ __launch_bounds__(1024, 1)
void scan_counts(const int* __restrict__ cnt, int* __restrict__ rowstart,
                 int* __restrict__ cursor, int N) {
    __shared__ int wsum[32];
    __shared__ int s_carry;
    const int tid = threadIdx.x, lane = tid & 31, wid = tid >> 5;
    if (tid == 0) s_carry = 0;
    __syncthreads();
    for (int base = 0; base < N; base += 4096) {
        int idx = base + tid * 4;
        int4 v = make_int4(0, 0, 0, 0);
        if (idx + 3 < N) v = *(const int4*)&cnt[idx];
        else {
            if (idx + 0 < N) v.x = cnt[idx + 0];
            if (idx + 1 < N) v.y = cnt[idx + 1];
            if (idx + 2 < N) v.z = cnt[idx + 2];
            if (idx + 3 < N) v.w = cnt[idx + 3];
        }
        int tsum = v.x + v.y + v.z + v.w;
        int x = tsum;
        #pragma unroll
        for (int off = 1; off < 32; off <<= 1) {
            int y = __shfl_up_sync(0xFFFFFFFFu, x, off);
            if (lane >= off) x += y;
        }
        if (lane == 31) wsum[wid] = x;
        __syncthreads();
        if (wid == 0) {
            int w = wsum[lane];
            #pragma unroll
            for (int off = 1; off < 32; off <<= 1) {
                int y = __shfl_up_sync(0xFFFFFFFFu, w, off);
                if (lane >= off) w += y;
            }
            wsum[lane] = w;
        }
        __syncthreads();
        int carry = s_carry;
        int excl = carry + (wid > 0 ? wsum[wid - 1] : 0) + x - tsum;
        int e0 = excl;
        int e1 = e0 + v.x;
        int e2 = e1 + v.y;
        int e3 = e2 + v.z;
        if (idx + 3 < N) {
            *(int4*)&rowstart[idx] = make_int4(e0, e1, e2, e3);
            *(int4*)&cursor[idx]   = make_int4(e0, e1, e2, e3);
        } else {
            if (idx + 0 < N) { rowstart[idx + 0] = e0; cursor[idx + 0] = e0; }
            if (idx + 1 < N) { rowstart[idx + 1] = e1; cursor[idx + 1] = e1; }
            if (idx + 2 < N) { rowstart[idx + 2] = e2; cursor[idx + 2] = e2; }
            if (idx + 3 < N) { rowstart[idx + 3] = e3; cursor[idx + 3] = e3; }
        }
        __syncthreads();
        if (tid == 1023) s_carry = carry + wsum[31];
        __syncthreads();
    }
    if (tid == 0) rowstart[N] = s_carry;
}

__global__ void scatter_edges(const int* __restrict__ ei, int E, int Etot,
                              int* __restrict__ cursor,
                              int* __restrict__ sorted_src) {
    int stride = gridDim.x * blockDim.x;
    for (int i = blockIdx.x * blockDim.x + threadIdx.x; i < Etot; i += stride) {
        int s, d;
        if (i < E) { s = ei[i]; d = ei[E + i]; }
        else       { s = d = i - E; }
        int pos = atomicAdd(&cursor[d], 1);
        sorted_src[pos] = s;
    }
}

// ---------------------------------------------------------------------------
// HGEMM: C_h[M,Ncols] = A_h[M,128] @ W (WT[n][k] fp16), fp32 acc.
// mma.sync m16n8k16. Block 128x64, 8 warps (4M x 2N), warp tile 32x32.
// ---------------------------------------------------------------------------
#define AS_STRIDE 40
#define BS_STRIDE 136

__device__ __forceinline__ void mma16816(float* c, const unsigned int* a,
                                         unsigned int b0, unsigned int b1) {
    asm volatile(
        "mma.sync.aligned.m16n8k16.row.col.f32.f16.f16.f32 "
        "{%0,%1,%2,%3}, {%4,%5,%6,%7}, {%8,%9}, {%0,%1,%2,%3};"
        : "+f"(c[0]), "+f"(c[1]), "+f"(c[2]), "+f"(c[3])
        : "r"(a[0]), "r"(a[1]), "r"(a[2]), "r"(a[3]), "r"(b0), "r"(b1));
}

__global__ __launch_bounds__(256, 1)
void hgemm_k128(const __half* __restrict__ A, const __half* __restrict__ WT,
                __half* __restrict__ C, int M, int Ncols) {
    __shared__ __half As[128 * AS_STRIDE];
    __shared__ __half Bs[64 * BS_STRIDE];

    const int tid  = threadIdx.x;
    const int lane = tid & 31;
    const int wid  = tid >> 5;
    const int row0 = blockIdx.x * 128;
    const int col0 = blockIdx.y * 64;
    const int wm = (wid & 3) * 32;
    const int wn = (wid >> 2) * 32;

    {
        int n = tid >> 2;
        int p = (tid & 3) * 32;
        const uint4* src = (const uint4*)&WT[(size_t)(col0 + n) * 128 + p];
        uint4* dst = (uint4*)&Bs[n * BS_STRIDE + p];
        dst[0] = src[0]; dst[1] = src[1]; dst[2] = src[2]; dst[3] = src[3];
    }

    float acc[2][4][4];
    #pragma unroll
    for (int mt = 0; mt < 2; mt++)
        #pragma unroll
        for (int nt = 0; nt < 4; nt++)
            #pragma unroll
            for (int q = 0; q < 4; q++) acc[mt][nt][q] = 0.0f;

    const int arow = tid >> 1;
    const int acol = (tid & 1) * 16;
    const int frow = lane >> 2;
    const int fcol = 2 * (lane & 3);

    for (int kc = 0; kc < 128; kc += 32) {
        uint4 v0 = make_uint4(0, 0, 0, 0), v1 = make_uint4(0, 0, 0, 0);
        int gr = row0 + arow;
        if (gr < M) {
            const uint4* s = (const uint4*)&A[(size_t)gr * 128 + kc + acol];
            v0 = s[0]; v1 = s[1];
        }
        __syncthreads();
        *(uint4*)&As[arow * AS_STRIDE + acol]     = v0;
        *(uint4*)&As[arow * AS_STRIDE + acol + 8] = v1;
        __syncthreads();

        #pragma unroll
        for (int kk = 0; kk < 32; kk += 16) {
            unsigned int a[2][4];
            #pragma unroll
            for (int mt = 0; mt < 2; mt++) {
                int r = wm + mt * 16 + frow;
                int c = kk + fcol;
                a[mt][0] = *(const unsigned int*)&As[r * AS_STRIDE + c];
                a[mt][1] = *(const unsigned int*)&As[(r + 8) * AS_STRIDE + c];
                a[mt][2] = *(const unsigned int*)&As[r * AS_STRIDE + c + 8];
                a[mt][3] = *(const unsigned int*)&As[(r + 8) * AS_STRIDE + c + 8];
            }
            #pragma unroll
            for (int nt = 0; nt < 4; nt++) {
                int n = wn + nt * 8 + frow;
                int ck = kc + kk + fcol;
                unsigned int b0 = *(const unsigned int*)&Bs[n * BS_STRIDE + ck];
                unsigned int b1 = *(const unsigned int*)&Bs[n * BS_STRIDE + ck + 8];
                mma16816(acc[0][nt], a[0], b0, b1);
                mma16816(acc[1][nt], a[1], b0, b1);
            }
        }
    }

    #pragma unroll
    for (int mt = 0; mt < 2; mt++) {
        int r = row0 + wm + mt * 16 + frow;
        #pragma unroll
        for (int nt = 0; nt < 4; nt++) {
            int c = col0 + wn + nt * 8 + fcol;
            if (r < M) {
                __half2 h = __floats2half2_rn(acc[mt][nt][0], acc[mt][nt][1]);
                *(__half2*)&C[(size_t)r * Ncols + c] = h;
            }
            if (r + 8 < M) {
                __half2 h = __floats2half2_rn(acc[mt][nt][2], acc[mt][nt][3]);
                *(__half2*)&C[(size_t)(r + 8) * Ncols + c] = h;
            }
        }
    }
}

// ---------------------------------------------------------------------------
// Node attention terms: warp per node, vectorized fp16 loads.
// ---------------------------------------------------------------------------
__global__ __launch_bounds__(256)
void node_alpha1(const __half* __restrict__ h,
                 const float* __restrict__ a_src,
                 const float* __restrict__ a_dst,
                 float* __restrict__ al_s,
                 float* __restrict__ al_d, int N) {
    int w = (blockIdx.x * blockDim.x + threadIdx.x) >> 5;
    int lane = threadIdx.x & 31;
    if (w >= N) return;
    uint2 raw = *(const uint2*)&h[(size_t)w * 128 + lane * 4];
    float2 f0 = __half22float2(*(const __half2*)&raw.x);
    float2 f1 = __half22float2(*(const __half2*)&raw.y);
    float4 asv = *(const float4*)&a_src[lane * 4];
    float4 adv = *(const float4*)&a_dst[lane * 4];
    float ps = f0.x * asv.x + f0.y * asv.y + f1.x * asv.z + f1.y * asv.w;
    float pd = f0.x * adv.x + f0.y * adv.y + f1.x * adv.z + f1.y * adv.w;
    // reduce within 8-lane group (one head = 32 channels = 8 lanes x 4)
    #pragma unroll
    for (int off = 4; off > 0; off >>= 1) {
        ps += __shfl_xor_sync(0xFFFFFFFFu, ps, off);
        pd += __shfl_xor_sync(0xFFFFFFFFu, pd, off);
    }
    if ((lane & 7) == 0) {
        int hd = lane >> 3;
        al_s[w * 4 + hd] = ps;
        al_d[w * 4 + hd] = pd;
    }
}

__global__ __launch_bounds__(256)
void node_alpha2(const __half* __restrict__ h,
                 const float* __restrict__ a_src,
                 const float* __restrict__ a_dst,
                 float* __restrict__ al_s,
                 float* __restrict__ al_d, int N) {
    int w = (blockIdx.x * blockDim.x + threadIdx.x) >> 5;
    int lane = threadIdx.x & 31;
    if (w >= N) return;
    uint4 raw = *(const uint4*)&h[(size_t)w * 256 + lane * 8];
    float2 f0 = __half22float2(*(const __half2*)&raw.x);
    float2 f1 = __half22float2(*(const __half2*)&raw.y);
    float2 f2 = __half22float2(*(const __half2*)&raw.z);
    float2 f3 = __half22float2(*(const __half2*)&raw.w);
    float4 s0 = *(const float4*)&a_src[lane * 8];
    float4 s1 = *(const float4*)&a_src[lane * 8 + 4];
    float4 d0 = *(const float4*)&a_dst[lane * 8];
    float4 d1 = *(const float4*)&a_dst[lane * 8 + 4];
    float ps = f0.x * s0.x + f0.y * s0.y + f1.x * s0.z + f1.y * s0.w
             + f2.x * s1.x + f2.y * s1.y + f3.x * s1.z + f3.y * s1.w;
    float pd = f0.x * d0.x + f0.y * d0.y + f1.x * d0.z + f1.y * d0.w
             + f2.x * d1.x + f2.y * d1.y + f3.x * d1.z + f3.y * d1.w;
    #pragma unroll
    for (int off = 16; off > 0; off >>= 1) {
        ps += __shfl_xor_sync(0xFFFFFFFFu, ps, off);
        pd += __shfl_xor_sync(0xFFFFFFFFu, pd, off);
    }
    if (lane == 0) {
        al_s[w] = ps;
        al_d[w] = pd;
    }
}

// ---------------------------------------------------------------------------
// Layer-1 fused gather: out = (sum e_j * v_j) / (sum e_j + 1e-16).
// Warp per dst node, single pass, software-pipelined. fp16 out + bias + relu.
// ---------------------------------------------------------------------------
__global__ __launch_bounds__(256)
void gather_agg1(const int* __restrict__ rowstart, const int* __restrict__ ssrc,
                 const float* __restrict__ als, const float* __restrict__ ald,
                 const __half* __restrict__ hlin, const float* __restrict__ bias,
                 __half* __restrict__ outp, int N) {
    int w = (blockIdx.x * blockDim.x + threadIdx.x) >> 5;
    int lane = threadIdx.x & 31;
    if (w >= N) return;
    const int beg = rowstart[w];
    const int end = rowstart[w + 1];
    const int head = lane >> 3;
    const float ad_h = ald[w * 4 + head];

    float ssum = 0.f;
    float4 acc = make_float4(0.f, 0.f, 0.f, 0.f);

    // prefetch j = beg
    int sn0 = 0; float al0 = 0.f; uint2 raw0 = make_uint2(0, 0);
    if (beg < end) {
        sn0 = ssrc[beg];
        al0 = als[sn0 * 4 + head];
        raw0 = *(const uint2*)&hlin[(size_t)sn0 * 128 + lane * 4];
    }
    for (int j = beg; j < end; j++) {
        float alv = al0;
        uint2 raw = raw0;
        int jn = j + 1;
        if (jn < end) {
            sn0 = ssrc[jn];
            al0 = als[sn0 * 4 + head];
            raw0 = *(const uint2*)&hlin[(size_t)sn0 * 128 + lane * 4];
        }
        float e = __expf(lrelu(alv + ad_h));
        ssum += e;
        float2 f0 = __half22float2(*(const __half2*)&raw.x);
        float2 f1 = __half22float2(*(const __half2*)&raw.y);
        acc.x = fmaf(e, f0.x, acc.x);
        acc.y = fmaf(e, f0.y, acc.y);
        acc.z = fmaf(e, f1.x, acc.z);
        acc.w = fmaf(e, f1.y, acc.w);
    }
    const float inv = 1.0f / (ssum + 1e-16f);
    float4 bb = *(const float4*)&bias[lane * 4];
    acc.x = fmaxf(fmaf(acc.x, inv, bb.x), 0.f);
    acc.y = fmaxf(fmaf(acc.y, inv, bb.y), 0.f);
    acc.z = fmaxf(fmaf(acc.z, inv, bb.z), 0.f);
    acc.w = fmaxf(fmaf(acc.w, inv, bb.w), 0.f);
    __half2 h0 = __floats2half2_rn(acc.x, acc.y);
    __half2 h1 = __floats2half2_rn(acc.z, acc.w);
    uint2 u;
    u.x = *(unsigned int*)&h0;
    u.y = *(unsigned int*)&h1;
    *(uint2*)&outp[(size_t)w * 128 + lane * 4] = u;
}

// ---------------------------------------------------------------------------
// Layer-2 fused gather. Warp per dst node, single pass, pipelined. fp32 out.
// ---------------------------------------------------------------------------
__global__ __launch_bounds__(256)
void gather_agg2(const int* __restrict__ rowstart, const int* __restrict__ ssrc,
                 const float* __restrict__ als, const float* __restrict__ ald,
                 const __half* __restrict__ hlin, const float* __restrict__ bias,
                 float* __restrict__ outp, int N) {
    int w = (blockIdx.x * blockDim.x + threadIdx.x) >> 5;
    int lane = threadIdx.x & 31;
    if (w >= N) return;
    const int beg = rowstart[w];
    const int end = rowstart[w + 1];
    const float ad = ald[w];

    float ssum = 0.f;
    float4 a0 = make_float4(0.f, 0.f, 0.f, 0.f);
    float4 a1 = make_float4(0.f, 0.f, 0.f, 0.f);

    int sn0 = 0; float al0 = 0.f; uint4 raw0 = make_uint4(0, 0, 0, 0);
    if (beg < end) {
        sn0 = ssrc[beg];
        al0 = als[sn0];
        raw0 = *(const uint4*)&hlin[(size_t)sn0 * 256 + lane * 8];
    }
    for (int j = beg; j < end; j++) {
        float alv = al0;
        uint4 raw = raw0;
        int jn = j + 1;
        if (jn < end) {
            sn0 = ssrc[jn];
            al0 = als[sn0];
            raw0 = *(const uint4*)&hlin[(size_t)sn0 * 256 + lane * 8];
        }
        float e = __expf(lrelu(alv + ad));
        ssum += e;
        float2 f0 = __half22float2(*(const __half2*)&raw.x);
        float2 f1 = __half22float2(*(const __half2*)&raw.y);
        float2 f2 = __half22float2(*(const __half2*)&raw.z);
        float2 f3 = __half22float2(*(const __half2*)&raw.w);
        a0.x = fmaf(e, f0.x, a0.x);
        a0.y = fmaf(e, f0.y, a0.y);
        a0.z = fmaf(e, f1.x, a0.z);
        a0.w = fmaf(e, f1.y, a0.w);
        a1.x = fmaf(e, f2.x, a1.x);
        a1.y = fmaf(e, f2.y, a1.y);
        a1.z = fmaf(e, f3.x, a1.z);
        a1.w = fmaf(e, f3.y, a1.w);
    }
    const float inv = 1.0f / (ssum + 1e-16f);
    float4 b0 = *(const float4*)&bias[lane * 8];
    float4 b1v = *(const float4*)&bias[lane * 8 + 4];
    a0.x = fmaf(a0.x, inv, b0.x);
    a0.y = fmaf(a0.y, inv, b0.y);
    a0.z = fmaf(a0.z, inv, b0.z);
    a0.w = fmaf(a0.w, inv, b0.w);
    a1.x = fmaf(a1.x, inv, b1v.x);
    a1.y = fmaf(a1.y, inv, b1v.y);
    a1.z = fmaf(a1.z, inv, b1v.z);
    a1.w = fmaf(a1.w, inv, b1v.w);
    float* op = &outp[(size_t)w * 256 + lane * 8];
    *(float4*)&op[0] = a0;
    *(float4*)&op[4] = a1;
}

// ---------------------------------------------------------------------------
// Launch
// ---------------------------------------------------------------------------
extern "C" void kernel_launch(void* const* d_in, const int* in_sizes, int n_in,
                              void* d_out, int out_size) {
    const float* x   = (const float*)d_in[0];
    const int*   ei  = (const int*)d_in[1];
    const float* W1  = (const float*)d_in[2];
    const float* as1 = (const float*)d_in[3];
    const float* ad1 = (const float*)d_in[4];
    const float* b1  = (const float*)d_in[5];
    const float* W2  = (const float*)d_in[6];
    const float* as2 = (const float*)d_in[7];
    const float* ad2 = (const float*)d_in[8];
    const float* b2  = (const float*)d_in[9];
    float* out = (float*)d_out;

    const int N    = in_sizes[0] / 128;   // 50000
    const int E    = in_sizes[1] / 2;     // 1600000
    const int Etot = E + N;               // 1650000

    float *als1p, *ald1p, *als2p, *ald2p;
    __half *xh, *wt1h, *wt2h, *hlin1, *agg1h, *hlin2;
    int *cntp, *rowp, *curp, *ssrcp;
    cudaGetSymbolAddress((void**)&xh,    g_xh);
    cudaGetSymbolAddress((void**)&wt1h,  g_wt1h);
    cudaGetSymbolAddress((void**)&wt2h,  g_wt2h);
    cudaGetSymbolAddress((void**)&hlin1, g_hlin1);
    cudaGetSymbolAddress((void**)&als1p, g_als1);
    cudaGetSymbolAddress((void**)&ald1p, g_ald1);
    cudaGetSymbolAddress((void**)&agg1h, g_agg1h);
    cudaGetSymbolAddress((void**)&hlin2, g_hlin2);
    cudaGetSymbolAddress((void**)&als2p, g_als2);
    cudaGetSymbolAddress((void**)&ald2p, g_ald2);
    cudaGetSymbolAddress((void**)&cntp,  g_count);
    cudaGetSymbolAddress((void**)&rowp,  g_rowstart);
    cudaGetSymbolAddress((void**)&curp,  g_cursor);
    cudaGetSymbolAddress((void**)&ssrcp, g_sorted_src);

    const int NW_BLOCKS = (N * 32 + 255) / 256;
    const int EDGE_BLOCKS = (Etot / 4 + 255) / 256;   // ~4 edges per thread

    // --- conversions ---
    cvt_f2h<<<(N * 128 / 4 + 255) / 256, 256>>>(x, xh, N * 128 / 4);
    cvt_wt<<<(128 * 128 + 255) / 256, 256>>>(W1, wt1h, 128);
    cvt_wt<<<(128 * 256 + 255) / 256, 256>>>(W2, wt2h, 256);

    // --- CSR build ---
    cudaMemsetAsync(cntp, 0, (size_t)N * sizeof(int));
    hist_dst<<<EDGE_BLOCKS, 256>>>(ei, E, Etot, cntp);
    scan_counts<<<1, 1024>>>(cntp, rowp, curp, N);
    scatter_edges<<<EDGE_BLOCKS, 256>>>(ei, E, Etot, curp, ssrcp);

    // --- layer 1 ---
    {
        dim3 grid((N + 127) / 128, 2);
        hgemm_k128<<<grid, 256>>>(xh, wt1h, hlin1, N, 128);
    }
    node_alpha1<<<NW_BLOCKS, 256>>>(hlin1, as1, ad1, als1p, ald1p, N);
    gather_agg1<<<NW_BLOCKS, 256>>>(rowp, ssrcp, als1p, ald1p, hlin1, b1, agg1h, N);

    // --- layer 2 ---
    {
        dim3 grid((N + 127) / 128, 4);
        hgemm_k128<<<grid, 256>>>(agg1h, wt2h, hlin2, N, 256);
    }
    node_alpha2<<<NW_BLOCKS, 256>>>(hlin2, as2, ad2, als2p, ald2p, N);
    gather_agg2<<<NW_BLOCKS, 256>>>(rowp, ssrcp, als2p, ald2p, hlin2, b2, out, N);
}

// round 7
// speedup vs baseline: 4.5158x; 1.1957x over previous
#include <cuda_runtime.h>
#include <cuda_fp16.h>

// ---------------------------------------------------------------------------
// GAT encoder: 2x GATConv (4 heads x 32, then 1 head x 256), ReLU between.
// N=50000 nodes, E=1.6M edges + N self-loops.
// R6: MLP=4 batched gather loops; CSR build forked onto a second stream
//     overlapping the cvt/GEMM1/alpha1 chain. HMMA GEMMs, fused gathers.
// ---------------------------------------------------------------------------

#define NNODES 50000
#define EMAX   1700000   // >= E + N

__device__ __align__(16) __half g_xh[NNODES * 128];
__device__ __align__(16) __half g_wt1h[128 * 128];
__device__ __align__(16) __half g_wt2h[256 * 128];
__device__ __align__(16) __half g_hlin1[NNODES * 128];
__device__ __align__(16) float  g_als1[NNODES * 4];
__device__ __align__(16) float  g_ald1[NNODES * 4];
__device__ __align__(16) __half g_agg1h[NNODES * 128];
__device__ __align__(16) __half g_hlin2[NNODES * 256];
__device__ __align__(16) float  g_als2[NNODES];
__device__ __align__(16) float  g_ald2[NNODES];
__device__ int g_count[NNODES];
__device__ int g_rowstart[NNODES + 1];
__device__ int g_cursor[NNODES];
__device__ int g_sorted_src[EMAX];

__device__ __forceinline__ float lrelu(float x) {
    return x > 0.0f ? x : 0.2f * x;
}

// ---------------------------------------------------------------------------
// Conversions
// ---------------------------------------------------------------------------
__global__ void cvt_f2h(const float* __restrict__ in, __half* __restrict__ out, int n4) {
    int i = blockIdx.x * blockDim.x + threadIdx.x;
    if (i >= n4) return;
    float4 v = *(const float4*)&in[i * 4];
    __half2 h0 = __floats2half2_rn(v.x, v.y);
    __half2 h1 = __floats2half2_rn(v.z, v.w);
    uint2 u;
    u.x = *(unsigned int*)&h0;
    u.y = *(unsigned int*)&h1;
    *(uint2*)&out[i * 4] = u;
}

__global__ void cvt_wt(const float* __restrict__ W, __half* __restrict__ WT, int Ncols) {
    int i = blockIdx.x * blockDim.x + threadIdx.x;
    int total = 128 * Ncols;
    if (i >= total) return;
    int n = i >> 7;
    int k = i & 127;
    WT[i] = __float2half(W[k * Ncols + n]);
}

// ---------------------------------------------------------------------------
// CSR build
// ---------------------------------------------------------------------------
__global__ void hist_dst(const int* __restrict__ ei, int E, int Etot,
                         int* __restrict__ cnt) {
    int stride = gridDim.x * blockDim.x;
    for (int i = blockIdx.x * blockDim.x + threadIdx.x; i < Etot; i += stride) {
        int d = (i < E) ? ei[E + i] : (i - E);
        atomicAdd(&cnt[d], 1);
    }
}

__global__ __launch_bounds__(1024, 1)
void scan_counts(const int* __restrict__ cnt, int* __restrict__ rowstart,
                 int* __restrict__ cursor, int N) {
    __shared__ int wsum[32];
    __shared__ int s_carry;
    const int tid = threadIdx.x, lane = tid & 31, wid = tid >> 5;
    if (tid == 0) s_carry = 0;
    __syncthreads();
    for (int base = 0; base < N; base += 4096) {
        int idx = base + tid * 4;
        int4 v = make_int4(0, 0, 0, 0);
        if (idx + 3 < N) v = *(const int4*)&cnt[idx];
        else {
            if (idx + 0 < N) v.x = cnt[idx + 0];
            if (idx + 1 < N) v.y = cnt[idx + 1];
            if (idx + 2 < N) v.z = cnt[idx + 2];
            if (idx + 3 < N) v.w = cnt[idx + 3];
        }
        int tsum = v.x + v.y + v.z + v.w;
        int x = tsum;
        #pragma unroll
        for (int off = 1; off < 32; off <<= 1) {
            int y = __shfl_up_sync(0xFFFFFFFFu, x, off);
            if (lane >= off) x += y;
        }
        if (lane == 31) wsum[wid] = x;
        __syncthreads();
        if (wid == 0) {
            int w = wsum[lane];
            #pragma unroll
            for (int off = 1; off < 32; off <<= 1) {
                int y = __shfl_up_sync(0xFFFFFFFFu, w, off);
                if (lane >= off) w += y;
            }
            wsum[lane] = w;
        }
        __syncthreads();
        int carry = s_carry;
        int excl = carry + (wid > 0 ? wsum[wid - 1] : 0) + x - tsum;
        int e0 = excl;
        int e1 = e0 + v.x;
        int e2 = e1 + v.y;
        int e3 = e2 + v.z;
        if (idx + 3 < N) {
            *(int4*)&rowstart[idx] = make_int4(e0, e1, e2, e3);
            *(int4*)&cursor[idx]   = make_int4(e0, e1, e2, e3);
        } else {
            if (idx + 0 < N) { rowstart[idx + 0] = e0; cursor[idx + 0] = e0; }
            if (idx + 1 < N) { rowstart[idx + 1] = e1; cursor[idx + 1] = e1; }
            if (idx + 2 < N) { rowstart[idx + 2] = e2; cursor[idx + 2] = e2; }
            if (idx + 3 < N) { rowstart[idx + 3] = e3; cursor[idx + 3] = e3; }
        }
        __syncthreads();
        if (tid == 1023) s_carry = carry + wsum[31];
        __syncthreads();
    }
    if (tid == 0) rowstart[N] = s_carry;
}

__global__ void scatter_edges(const int* __restrict__ ei, int E, int Etot,
                              int* __restrict__ cursor,
                              int* __restrict__ sorted_src) {
    int stride = gridDim.x * blockDim.x;
    for (int i = blockIdx.x * blockDim.x + threadIdx.x; i < Etot; i += stride) {
        int s, d;
        if (i < E) { s = ei[i]; d = ei[E + i]; }
        else       { s = d = i - E; }
        int pos = atomicAdd(&cursor[d], 1);
        sorted_src[pos] = s;
    }
}

// ---------------------------------------------------------------------------
// HGEMM: C_h[M,Ncols] = A_h[M,128] @ W (WT[n][k] fp16), fp32 acc.
// mma.sync m16n8k16. Block 128x64, 8 warps (4M x 2N), warp tile 32x32.
// ---------------------------------------------------------------------------
#define AS_STRIDE 40
#define BS_STRIDE 136

__device__ __forceinline__ void mma16816(float* c, const unsigned int* a,
                                         unsigned int b0, unsigned int b1) {
    asm volatile(
        "mma.sync.aligned.m16n8k16.row.col.f32.f16.f16.f32 "
        "{%0,%1,%2,%3}, {%4,%5,%6,%7}, {%8,%9}, {%0,%1,%2,%3};"
        : "+f"(c[0]), "+f"(c[1]), "+f"(c[2]), "+f"(c[3])
        : "r"(a[0]), "r"(a[1]), "r"(a[2]), "r"(a[3]), "r"(b0), "r"(b1));
}

__global__ __launch_bounds__(256, 1)
void hgemm_k128(const __half* __restrict__ A, const __half* __restrict__ WT,
                __half* __restrict__ C, int M, int Ncols) {
    __shared__ __half As[128 * AS_STRIDE];
    __shared__ __half Bs[64 * BS_STRIDE];

    const int tid  = threadIdx.x;
    const int lane = tid & 31;
    const int wid  = tid >> 5;
    const int row0 = blockIdx.x * 128;
    const int col0 = blockIdx.y * 64;
    const int wm = (wid & 3) * 32;
    const int wn = (wid >> 2) * 32;

    {
        int n = tid >> 2;
        int p = (tid & 3) * 32;
        const uint4* src = (const uint4*)&WT[(size_t)(col0 + n) * 128 + p];
        uint4* dst = (uint4*)&Bs[n * BS_STRIDE + p];
        dst[0] = src[0]; dst[1] = src[1]; dst[2] = src[2]; dst[3] = src[3];
    }

    float acc[2][4][4];
    #pragma unroll
    for (int mt = 0; mt < 2; mt++)
        #pragma unroll
        for (int nt = 0; nt < 4; nt++)
            #pragma unroll
            for (int q = 0; q < 4; q++) acc[mt][nt][q] = 0.0f;

    const int arow = tid >> 1;
    const int acol = (tid & 1) * 16;
    const int frow = lane >> 2;
    const int fcol = 2 * (lane & 3);

    for (int kc = 0; kc < 128; kc += 32) {
        uint4 v0 = make_uint4(0, 0, 0, 0), v1 = make_uint4(0, 0, 0, 0);
        int gr = row0 + arow;
        if (gr < M) {
            const uint4* s = (const uint4*)&A[(size_t)gr * 128 + kc + acol];
            v0 = s[0]; v1 = s[1];
        }
        __syncthreads();
        *(uint4*)&As[arow * AS_STRIDE + acol]     = v0;
        *(uint4*)&As[arow * AS_STRIDE + acol + 8] = v1;
        __syncthreads();

        #pragma unroll
        for (int kk = 0; kk < 32; kk += 16) {
            unsigned int a[2][4];
            #pragma unroll
            for (int mt = 0; mt < 2; mt++) {
                int r = wm + mt * 16 + frow;
                int c = kk + fcol;
                a[mt][0] = *(const unsigned int*)&As[r * AS_STRIDE + c];
                a[mt][1] = *(const unsigned int*)&As[(r + 8) * AS_STRIDE + c];
                a[mt][2] = *(const unsigned int*)&As[r * AS_STRIDE + c + 8];
                a[mt][3] = *(const unsigned int*)&As[(r + 8) * AS_STRIDE + c + 8];
            }
            #pragma unroll
            for (int nt = 0; nt < 4; nt++) {
                int n = wn + nt * 8 + frow;
                int ck = kc + kk + fcol;
                unsigned int b0 = *(const unsigned int*)&Bs[n * BS_STRIDE + ck];
                unsigned int b1 = *(const unsigned int*)&Bs[n * BS_STRIDE + ck + 8];
                mma16816(acc[0][nt], a[0], b0, b1);
                mma16816(acc[1][nt], a[1], b0, b1);
            }
        }
    }

    #pragma unroll
    for (int mt = 0; mt < 2; mt++) {
        int r = row0 + wm + mt * 16 + frow;
        #pragma unroll
        for (int nt = 0; nt < 4; nt++) {
            int c = col0 + wn + nt * 8 + fcol;
            if (r < M) {
                __half2 h = __floats2half2_rn(acc[mt][nt][0], acc[mt][nt][1]);
                *(__half2*)&C[(size_t)r * Ncols + c] = h;
            }
            if (r + 8 < M) {
                __half2 h = __floats2half2_rn(acc[mt][nt][2], acc[mt][nt][3]);
                *(__half2*)&C[(size_t)(r + 8) * Ncols + c] = h;
            }
        }
    }
}

// ---------------------------------------------------------------------------
// Node attention terms: warp per node, vectorized fp16 loads.
// ---------------------------------------------------------------------------
__global__ __launch_bounds__(256)
void node_alpha1(const __half* __restrict__ h,
                 const float* __restrict__ a_src,
                 const float* __restrict__ a_dst,
                 float* __restrict__ al_s,
                 float* __restrict__ al_d, int N) {
    int w = (blockIdx.x * blockDim.x + threadIdx.x) >> 5;
    int lane = threadIdx.x & 31;
    if (w >= N) return;
    uint2 raw = *(const uint2*)&h[(size_t)w * 128 + lane * 4];
    float2 f0 = __half22float2(*(const __half2*)&raw.x);
    float2 f1 = __half22float2(*(const __half2*)&raw.y);
    float4 asv = *(const float4*)&a_src[lane * 4];
    float4 adv = *(const float4*)&a_dst[lane * 4];
    float ps = f0.x * asv.x + f0.y * asv.y + f1.x * asv.z + f1.y * asv.w;
    float pd = f0.x * adv.x + f0.y * adv.y + f1.x * adv.z + f1.y * adv.w;
    #pragma unroll
    for (int off = 4; off > 0; off >>= 1) {
        ps += __shfl_xor_sync(0xFFFFFFFFu, ps, off);
        pd += __shfl_xor_sync(0xFFFFFFFFu, pd, off);
    }
    if ((lane & 7) == 0) {
        int hd = lane >> 3;
        al_s[w * 4 + hd] = ps;
        al_d[w * 4 + hd] = pd;
    }
}

__global__ __launch_bounds__(256)
void node_alpha2(const __half* __restrict__ h,
                 const float* __restrict__ a_src,
                 const float* __restrict__ a_dst,
                 float* __restrict__ al_s,
                 float* __restrict__ al_d, int N) {
    int w = (blockIdx.x * blockDim.x + threadIdx.x) >> 5;
    int lane = threadIdx.x & 31;
    if (w >= N) return;
    uint4 raw = *(const uint4*)&h[(size_t)w * 256 + lane * 8];
    float2 f0 = __half22float2(*(const __half2*)&raw.x);
    float2 f1 = __half22float2(*(const __half2*)&raw.y);
    float2 f2 = __half22float2(*(const __half2*)&raw.z);
    float2 f3 = __half22float2(*(const __half2*)&raw.w);
    float4 s0 = *(const float4*)&a_src[lane * 8];
    float4 s1 = *(const float4*)&a_src[lane * 8 + 4];
    float4 d0 = *(const float4*)&a_dst[lane * 8];
    float4 d1 = *(const float4*)&a_dst[lane * 8 + 4];
    float ps = f0.x * s0.x + f0.y * s0.y + f1.x * s0.z + f1.y * s0.w
             + f2.x * s1.x + f2.y * s1.y + f3.x * s1.z + f3.y * s1.w;
    float pd = f0.x * d0.x + f0.y * d0.y + f1.x * d0.z + f1.y * d0.w
             + f2.x * d1.x + f2.y * d1.y + f3.x * d1.z + f3.y * d1.w;
    #pragma unroll
    for (int off = 16; off > 0; off >>= 1) {
        ps += __shfl_xor_sync(0xFFFFFFFFu, ps, off);
        pd += __shfl_xor_sync(0xFFFFFFFFu, pd, off);
    }
    if (lane == 0) {
        al_s[w] = ps;
        al_d[w] = pd;
    }
}

// ---------------------------------------------------------------------------
// Layer-1 fused gather, MLP=4 batched. out = (sum e*v)/(sum e + 1e-16).
// ---------------------------------------------------------------------------
__global__ __launch_bounds__(256)
void gather_agg1(const int* __restrict__ rowstart, const int* __restrict__ ssrc,
                 const float* __restrict__ als, const float* __restrict__ ald,
                 const __half* __restrict__ hlin, const float* __restrict__ bias,
                 __half* __restrict__ outp, int N) {
    int w = (blockIdx.x * blockDim.x + threadIdx.x) >> 5;
    int lane = threadIdx.x & 31;
    if (w >= N) return;
    const int beg = rowstart[w];
    const int end = rowstart[w + 1];
    const int head = lane >> 3;
    const float ad_h = ald[w * 4 + head];

    float ssum = 0.f;
    float4 acc = make_float4(0.f, 0.f, 0.f, 0.f);

    int j = beg;
    for (; j + 4 <= end; j += 4) {
        int sn0 = ssrc[j], sn1 = ssrc[j + 1], sn2 = ssrc[j + 2], sn3 = ssrc[j + 3];
        float al0 = als[sn0 * 4 + head];
        float al1 = als[sn1 * 4 + head];
        float al2 = als[sn2 * 4 + head];
        float al3 = als[sn3 * 4 + head];
        uint2 r0 = *(const uint2*)&hlin[(size_t)sn0 * 128 + lane * 4];
        uint2 r1 = *(const uint2*)&hlin[(size_t)sn1 * 128 + lane * 4];
        uint2 r2 = *(const uint2*)&hlin[(size_t)sn2 * 128 + lane * 4];
        uint2 r3 = *(const uint2*)&hlin[(size_t)sn3 * 128 + lane * 4];
        float e0 = __expf(lrelu(al0 + ad_h));
        float e1 = __expf(lrelu(al1 + ad_h));
        float e2 = __expf(lrelu(al2 + ad_h));
        float e3 = __expf(lrelu(al3 + ad_h));
        ssum += (e0 + e1) + (e2 + e3);
        float2 a, b;
        a = __half22float2(*(const __half2*)&r0.x);
        b = __half22float2(*(const __half2*)&r0.y);
        acc.x = fmaf(e0, a.x, acc.x); acc.y = fmaf(e0, a.y, acc.y);
        acc.z = fmaf(e0, b.x, acc.z); acc.w = fmaf(e0, b.y, acc.w);
        a = __half22float2(*(const __half2*)&r1.x);
        b = __half22float2(*(const __half2*)&r1.y);
        acc.x = fmaf(e1, a.x, acc.x); acc.y = fmaf(e1, a.y, acc.y);
        acc.z = fmaf(e1, b.x, acc.z); acc.w = fmaf(e1, b.y, acc.w);
        a = __half22float2(*(const __half2*)&r2.x);
        b = __half22float2(*(const __half2*)&r2.y);
        acc.x = fmaf(e2, a.x, acc.x); acc.y = fmaf(e2, a.y, acc.y);
        acc.z = fmaf(e2, b.x, acc.z); acc.w = fmaf(e2, b.y, acc.w);
        a = __half22float2(*(const __half2*)&r3.x);
        b = __half22float2(*(const __half2*)&r3.y);
        acc.x = fmaf(e3, a.x, acc.x); acc.y = fmaf(e3, a.y, acc.y);
        acc.z = fmaf(e3, b.x, acc.z); acc.w = fmaf(e3, b.y, acc.w);
    }
    for (; j < end; j++) {
        int sn = ssrc[j];
        float e = __expf(lrelu(als[sn * 4 + head] + ad_h));
        uint2 r = *(const uint2*)&hlin[(size_t)sn * 128 + lane * 4];
        ssum += e;
        float2 a = __half22float2(*(const __half2*)&r.x);
        float2 b = __half22float2(*(const __half2*)&r.y);
        acc.x = fmaf(e, a.x, acc.x); acc.y = fmaf(e, a.y, acc.y);
        acc.z = fmaf(e, b.x, acc.z); acc.w = fmaf(e, b.y, acc.w);
    }
    const float inv = 1.0f / (ssum + 1e-16f);
    float4 bb = *(const float4*)&bias[lane * 4];
    acc.x = fmaxf(fmaf(acc.x, inv, bb.x), 0.f);
    acc.y = fmaxf(fmaf(acc.y, inv, bb.y), 0.f);
    acc.z = fmaxf(fmaf(acc.z, inv, bb.z), 0.f);
    acc.w = fmaxf(fmaf(acc.w, inv, bb.w), 0.f);
    __half2 h0 = __floats2half2_rn(acc.x, acc.y);
    __half2 h1 = __floats2half2_rn(acc.z, acc.w);
    uint2 u;
    u.x = *(unsigned int*)&h0;
    u.y = *(unsigned int*)&h1;
    *(uint2*)&outp[(size_t)w * 128 + lane * 4] = u;
}

// ---------------------------------------------------------------------------
// Layer-2 fused gather, MLP=4 batched. fp32 out.
// ---------------------------------------------------------------------------
__global__ __launch_bounds__(256)
void gather_agg2(const int* __restrict__ rowstart, const int* __restrict__ ssrc,
                 const float* __restrict__ als, const float* __restrict__ ald,
                 const __half* __restrict__ hlin, const float* __restrict__ bias,
                 float* __restrict__ outp, int N) {
    int w = (blockIdx.x * blockDim.x + threadIdx.x) >> 5;
    int lane = threadIdx.x & 31;
    if (w >= N) return;
    const int beg = rowstart[w];
    const int end = rowstart[w + 1];
    const float ad = ald[w];

    float ssum = 0.f;
    float4 a0 = make_float4(0.f, 0.f, 0.f, 0.f);
    float4 a1 = make_float4(0.f, 0.f, 0.f, 0.f);

    int j = beg;
    for (; j + 4 <= end; j += 4) {
        int sn0 = ssrc[j], sn1 = ssrc[j + 1], sn2 = ssrc[j + 2], sn3 = ssrc[j + 3];
        float al0 = als[sn0], al1 = als[sn1], al2 = als[sn2], al3 = als[sn3];
        uint4 r0 = *(const uint4*)&hlin[(size_t)sn0 * 256 + lane * 8];
        uint4 r1 = *(const uint4*)&hlin[(size_t)sn1 * 256 + lane * 8];
        uint4 r2 = *(const uint4*)&hlin[(size_t)sn2 * 256 + lane * 8];
        uint4 r3 = *(const uint4*)&hlin[(size_t)sn3 * 256 + lane * 8];
        float e0 = __expf(lrelu(al0 + ad));
        float e1 = __expf(lrelu(al1 + ad));
        float e2 = __expf(lrelu(al2 + ad));
        float e3 = __expf(lrelu(al3 + ad));
        ssum += (e0 + e1) + (e2 + e3);
        #define ACC8(rv, ev)                                                    \
        {                                                                       \
            float2 f0 = __half22float2(*(const __half2*)&rv.x);                 \
            float2 f1 = __half22float2(*(const __half2*)&rv.y);                 \
            float2 f2 = __half22float2(*(const __half2*)&rv.z);                 \
            float2 f3 = __half22float2(*(const __half2*)&rv.w);                 \
            a0.x = fmaf(ev, f0.x, a0.x); a0.y = fmaf(ev, f0.y, a0.y);           \
            a0.z = fmaf(ev, f1.x, a0.z); a0.w = fmaf(ev, f1.y, a0.w);           \
            a1.x = fmaf(ev, f2.x, a1.x); a1.y = fmaf(ev, f2.y, a1.y);           \
            a1.z = fmaf(ev, f3.x, a1.z); a1.w = fmaf(ev, f3.y, a1.w);           \
        }
        ACC8(r0, e0)
        ACC8(r1, e1)
        ACC8(r2, e2)
        ACC8(r3, e3)
    }
    for (; j < end; j++) {
        int sn = ssrc[j];
        float e = __expf(lrelu(als[sn] + ad));
        uint4 r = *(const uint4*)&hlin[(size_t)sn * 256 + lane * 8];
        ssum += e;
        ACC8(r, e)
    }
    #undef ACC8
    const float inv = 1.0f / (ssum + 1e-16f);
    float4 b0 = *(const float4*)&bias[lane * 8];
    float4 b1v = *(const float4*)&bias[lane * 8 + 4];
    a0.x = fmaf(a0.x, inv, b0.x);
    a0.y = fmaf(a0.y, inv, b0.y);
    a0.z = fmaf(a0.z, inv, b0.z);
    a0.w = fmaf(a0.w, inv, b0.w);
    a1.x = fmaf(a1.x, inv, b1v.x);
    a1.y = fmaf(a1.y, inv, b1v.y);
    a1.z = fmaf(a1.z, inv, b1v.z);
    a1.w = fmaf(a1.w, inv, b1v.w);
    float* op = &outp[(size_t)w * 256 + lane * 8];
    *(float4*)&op[0] = a0;
    *(float4*)&op[4] = a1;
}

// ---------------------------------------------------------------------------
// Launch
// ---------------------------------------------------------------------------
extern "C" void kernel_launch(void* const* d_in, const int* in_sizes, int n_in,
                              void* d_out, int out_size) {
    const float* x   = (const float*)d_in[0];
    const int*   ei  = (const int*)d_in[1];
    const float* W1  = (const float*)d_in[2];
    const float* as1 = (const float*)d_in[3];
    const float* ad1 = (const float*)d_in[4];
    const float* b1  = (const float*)d_in[5];
    const float* W2  = (const float*)d_in[6];
    const float* as2 = (const float*)d_in[7];
    const float* ad2 = (const float*)d_in[8];
    const float* b2  = (const float*)d_in[9];
    float* out = (float*)d_out;

    const int N    = in_sizes[0] / 128;   // 50000
    const int E    = in_sizes[1] / 2;     // 1600000
    const int Etot = E + N;               // 1650000

    float *als1p, *ald1p, *als2p, *ald2p;
    __half *xh, *wt1h, *wt2h, *hlin1, *agg1h, *hlin2;
    int *cntp, *rowp, *curp, *ssrcp;
    cudaGetSymbolAddress((void**)&xh,    g_xh);
    cudaGetSymbolAddress((void**)&wt1h,  g_wt1h);
    cudaGetSymbolAddress((void**)&wt2h,  g_wt2h);
    cudaGetSymbolAddress((void**)&hlin1, g_hlin1);
    cudaGetSymbolAddress((void**)&als1p, g_als1);
    cudaGetSymbolAddress((void**)&ald1p, g_ald1);
    cudaGetSymbolAddress((void**)&agg1h, g_agg1h);
    cudaGetSymbolAddress((void**)&hlin2, g_hlin2);
    cudaGetSymbolAddress((void**)&als2p, g_als2);
    cudaGetSymbolAddress((void**)&ald2p, g_ald2);
    cudaGetSymbolAddress((void**)&cntp,  g_count);
    cudaGetSymbolAddress((void**)&rowp,  g_rowstart);
    cudaGetSymbolAddress((void**)&curp,  g_cursor);
    cudaGetSymbolAddress((void**)&ssrcp, g_sorted_src);

    // Stream/event resources created once (outside graph capture: the
    // harness's correctness call runs first). Work is identical every call.
    static cudaStream_t s2 = nullptr;
    static cudaEvent_t ev_fork = nullptr, ev_join = nullptr;
    if (s2 == nullptr) {
        cudaStreamCreateWithFlags(&s2, cudaStreamNonBlocking);
        cudaEventCreateWithFlags(&ev_fork, cudaEventDisableTiming);
        cudaEventCreateWithFlags(&ev_join, cudaEventDisableTiming);
    }

    const int NW_BLOCKS = (N * 32 + 255) / 256;
    const int EDGE_BLOCKS = (Etot / 4 + 255) / 256;

    // --- fork: CSR build on s2, concurrent with cvt/GEMM1/alpha1 ---
    cudaEventRecord(ev_fork, 0);
    cudaStreamWaitEvent(s2, ev_fork, 0);
    cudaMemsetAsync(cntp, 0, (size_t)N * sizeof(int), s2);
    hist_dst<<<EDGE_BLOCKS, 256, 0, s2>>>(ei, E, Etot, cntp);
    scan_counts<<<1, 1024, 0, s2>>>(cntp, rowp, curp, N);
    scatter_edges<<<EDGE_BLOCKS, 256, 0, s2>>>(ei, E, Etot, curp, ssrcp);
    cudaEventRecord(ev_join, s2);

    // --- main stream: conversions + GEMM1 + alpha1 ---
    cvt_f2h<<<(N * 128 / 4 + 255) / 256, 256>>>(x, xh, N * 128 / 4);
    cvt_wt<<<(128 * 128 + 255) / 256, 256>>>(W1, wt1h, 128);
    cvt_wt<<<(128 * 256 + 255) / 256, 256>>>(W2, wt2h, 256);
    {
        dim3 grid((N + 127) / 128, 2);
        hgemm_k128<<<grid, 256>>>(xh, wt1h, hlin1, N, 128);
    }
    node_alpha1<<<NW_BLOCKS, 256>>>(hlin1, as1, ad1, als1p, ald1p, N);

    // --- join: gather needs CSR ---
    cudaStreamWaitEvent(0, ev_join, 0);
    gather_agg1<<<NW_BLOCKS, 256>>>(rowp, ssrcp, als1p, ald1p, hlin1, b1, agg1h, N);

    // --- layer 2 ---
    {
        dim3 grid((N + 127) / 128, 4);
        hgemm_k128<<<grid, 256>>>(agg1h, wt2h, hlin2, N, 256);
    }
    node_alpha2<<<NW_BLOCKS, 256>>>(hlin2, as2, ad2, als2p, ald2p, N);
    gather_agg2<<<NW_BLOCKS, 256>>>(rowp, ssrcp, als2p, ald2p, hlin2, b2, out, N);
}